// round 11
// baseline (speedup 1.0000x reference)
#include <cuda_runtime.h>
#include <cstdint>

// ---------------------------------------------------------------------------
// Problem constants
// ---------------------------------------------------------------------------
#define EMBED   1024
#define NHEADS  16
#define HDIM    64
#define NBATCH  2
#define SEQ     2048
#define TOKENS  (NBATCH * SEQ)          // 4096
#define WELEMS  (EMBED * EMBED)         // 1048576
#define SCALE_ATTN 0.125f               // 1/sqrt(64)
#define SA 36                           // GEMM smem row stride (floats): 4*qid+tig banks, 16B aligned

// Flash-attention tiling
#define BQ   128
#define BKV  64
#define NJ   (SEQ / BKV)                // 32
#define SQ8  68                         // flash smem row stride (64 + 4)

// ---------------------------------------------------------------------------
// Scratch (static __device__ globals; no runtime allocation allowed)
// ---------------------------------------------------------------------------
__device__ float g_Wdq[4 * WELEMS];                                  // tf32-rounded dequant weights
__device__ int   g_absmax[4];
__device__ float g_QK[2 * (size_t)NBATCH * NHEADS * SEQ * HDIM];     // Q then K, [B,H,S,D]
__device__ float g_Vt[(size_t)NBATCH * NHEADS * HDIM * SEQ];         // [B,H,D,S]
__device__ float g_ctx[(size_t)TOKENS * EMBED];                      // [B,S,E]

// ---------------------------------------------------------------------------
// Helpers (target-portable PTX only: mma.sync sm_80+, cp.async sm_80+)
// ---------------------------------------------------------------------------
__device__ __forceinline__ uint32_t smem_u32(const void* p) {
    uint32_t a;
    asm("{ .reg .u64 t; cvta.to.shared.u64 t, %1; cvt.u32.u64 %0, t; }" : "=r"(a) : "l"(p));
    return a;
}

__device__ __forceinline__ float rna_tf32(float x) {
    float r;
    asm("cvt.rna.tf32.f32 %0, %1;" : "=f"(r) : "f"(x));
    return r;
}

__device__ __forceinline__ uint32_t rna_tf32_u(float x) {
    float r;
    asm("cvt.rna.tf32.f32 %0, %1;" : "=f"(r) : "f"(x));
    return __float_as_uint(r);
}

__device__ __forceinline__ void cp_async16(uint32_t saddr, const void* gaddr) {
    asm volatile("cp.async.cg.shared.global [%0], [%1], 16;"
                 :: "r"(saddr), "l"(gaddr) : "memory");
}

__device__ __forceinline__ void mma_tf32(float* d, const uint32_t* a, const uint32_t* b) {
    asm volatile(
        "mma.sync.aligned.m16n8k8.row.col.f32.tf32.tf32.f32 "
        "{%0,%1,%2,%3}, {%4,%5,%6,%7}, {%8,%9}, {%0,%1,%2,%3};"
        : "+f"(d[0]), "+f"(d[1]), "+f"(d[2]), "+f"(d[3])
        : "r"(a[0]), "r"(a[1]), "r"(a[2]), "r"(a[3]), "r"(b[0]), "r"(b[1]));
}

// ---------------------------------------------------------------------------
// Weight quantization (bit-faithful: s = max|W|/127, round-half-even, clip,
// dequantize), then RNA-round to tf32 so the MMA truncation is lossless.
// ---------------------------------------------------------------------------
__global__ void k_reset() { if (threadIdx.x < 4) g_absmax[threadIdx.x] = 0; }

__global__ void k_absmax(const float* __restrict__ w0, const float* __restrict__ w1,
                         const float* __restrict__ w2, const float* __restrict__ w3)
{
    const float* W = (blockIdx.y == 0) ? w0 : (blockIdx.y == 1) ? w1
                   : (blockIdx.y == 2) ? w2 : w3;
    float m = 0.0f;
    for (int i = blockIdx.x * blockDim.x + threadIdx.x; i < WELEMS;
         i += gridDim.x * blockDim.x)
        m = fmaxf(m, fabsf(W[i]));
    #pragma unroll
    for (int o = 16; o; o >>= 1) m = fmaxf(m, __shfl_xor_sync(0xffffffffu, m, o));
    if ((threadIdx.x & 31) == 0) atomicMax(&g_absmax[blockIdx.y], __float_as_int(m));
}

__global__ void k_dequant(const float* __restrict__ w0, const float* __restrict__ w1,
                          const float* __restrict__ w2, const float* __restrict__ w3)
{
    int sel = blockIdx.y;
    const float* W = (sel == 0) ? w0 : (sel == 1) ? w1 : (sel == 2) ? w2 : w3;
    float s = __int_as_float(g_absmax[sel]) / 127.0f;
    int i = (blockIdx.x * blockDim.x + threadIdx.x) * 4;
    float4 w = *(const float4*)&W[i];
    float4 r;
    r.x = rna_tf32(fminf(fmaxf(rintf(w.x / s), -128.0f), 127.0f) * s);
    r.y = rna_tf32(fminf(fmaxf(rintf(w.y / s), -128.0f), 127.0f) * s);
    r.z = rna_tf32(fminf(fmaxf(rintf(w.z / s), -128.0f), 127.0f) * s);
    r.w = rna_tf32(fminf(fmaxf(rintf(w.w / s), -128.0f), 127.0f) * s);
    *(float4*)&g_Wdq[(size_t)sel * WELEMS + i] = r;
}

// ---------------------------------------------------------------------------
// Fused Q/K/V projection GEMM (one launch, grid z in {0,1,2}).
// NS=3 cp.async pipeline (loads 2 iterations ahead), ONE barrier per k-iter:
//   wait(group i) -> __syncthreads (visibility + WAR guard) ->
//   issue loads for stage (i+2)%3 (the stage last read at iter i-1) ->
//   compute stage i%3.
// A fragments RNA-rounded post-LDS (bit-identical to pre-rounding in gmem).
// z in {0,1}: [B,H,S,D] into g_QK + z*off;  z==2: [B,H,D,S] into g_Vt.
// ---------------------------------------------------------------------------
__global__ __launch_bounds__(256, 2)
void gemm_proj(const float* __restrict__ A0, const float* __restrict__ A1,
               const float* __restrict__ A2,
               const float* __restrict__ b0, const float* __restrict__ b1,
               const float* __restrict__ b2)
{
    extern __shared__ float smem[];
    constexpr int STF = 256 * SA;          // floats per stage (A 128 rows + B 128 rows)

    const int tid  = threadIdx.x;
    const int wid  = tid >> 5, lane = tid & 31;
    const int wm   = wid & 1, wn = wid >> 1;
    const int qid  = lane >> 2, tig = lane & 3;
    const int z    = blockIdx.z;

    const float* A = (z == 0) ? A0 : (z == 1) ? A1 : A2;
    const float* bias = (z == 0) ? b0 : (z == 1) ? b1 : b2;
    const float* gA = A + (size_t)(blockIdx.y * 128) * EMBED;
    const float* gB = g_Wdq + (size_t)z * WELEMS + (size_t)(blockIdx.x * 128) * EMBED;

    float acc[4][4][4] = {};

    auto loadStage = [&](int s, int k0) {
        float* sAp = smem + s * STF;
        float* sBp = sAp + 128 * SA;
        const int r0 = tid >> 3, c = (tid & 7) * 4;
        #pragma unroll
        for (int it = 0; it < 4; ++it) {
            const int r = r0 + it * 32;
            cp_async16(smem_u32(sAp + r * SA + c), gA + (size_t)r * EMBED + k0 + c);
        }
        #pragma unroll
        for (int it = 0; it < 4; ++it) {
            const int r = r0 + it * 32;
            cp_async16(smem_u32(sBp + r * SA + c), gB + (size_t)r * EMBED + k0 + c);
        }
        asm volatile("cp.async.commit_group;" ::: "memory");
    };

    const int ns = EMBED / 32;             // 32 k-iterations
    loadStage(0, 0);
    loadStage(1, 32);
    for (int i = 0; i < ns; ++i) {
        if (i + 1 < ns) {
            asm volatile("cp.async.wait_group 1;" ::: "memory");   // group i done
        } else {
            asm volatile("cp.async.wait_group 0;" ::: "memory");
        }
        __syncthreads();                    // publish group i; all warps past iter i-1
        if (i + 2 < ns) loadStage((i + 2) % 3, (i + 2) * 32);

        const float* sAp = smem + (i % 3) * STF;
        const float* sBp = sAp + 128 * SA;
        #pragma unroll
        for (int ks = 0; ks < 4; ++ks) {
            const int k = ks * 8 + tig;
            uint32_t af[4][4], bf[4][2];
            #pragma unroll
            for (int mt = 0; mt < 4; ++mt) {
                const float* ap = sAp + (wm * 64 + mt * 16 + qid) * SA + k;
                af[mt][0] = rna_tf32_u(ap[0]);           // raw input -> tf32 RNA
                af[mt][1] = rna_tf32_u(ap[8 * SA]);
                af[mt][2] = rna_tf32_u(ap[4]);
                af[mt][3] = rna_tf32_u(ap[8 * SA + 4]);
            }
            #pragma unroll
            for (int nt = 0; nt < 4; ++nt) {
                const float* bp = sBp + (wn * 32 + nt * 8 + qid) * SA + k;
                bf[nt][0] = __float_as_uint(bp[0]);      // weights pre-rounded
                bf[nt][1] = __float_as_uint(bp[4]);
            }
            #pragma unroll
            for (int mt = 0; mt < 4; ++mt)
                #pragma unroll
                for (int nt = 0; nt < 4; ++nt)
                    mma_tf32(acc[mt][nt], af[mt], bf[nt]);
        }
    }

    #pragma unroll
    for (int mt = 0; mt < 4; ++mt) {
        const int m = blockIdx.y * 128 + wm * 64 + mt * 16 + qid;
        const int b = m >> 11, s2 = m & (SEQ - 1);
        #pragma unroll
        for (int nt = 0; nt < 4; ++nt) {
            const int n = blockIdx.x * 128 + wn * 32 + nt * 8 + tig * 2;
            const int h = n >> 6, d = n & (HDIM - 1);
            const float bb0 = bias[n], bb1 = bias[n + 1];
            const float c0 = rna_tf32(acc[mt][nt][0] + bb0);
            const float c1 = rna_tf32(acc[mt][nt][1] + bb1);
            const float c2 = rna_tf32(acc[mt][nt][2] + bb0);
            const float c3 = rna_tf32(acc[mt][nt][3] + bb1);
            if (z < 2) {
                float* C = g_QK + (size_t)z * ((size_t)NBATCH * NHEADS * SEQ * HDIM);
                const size_t base = ((size_t)b * NHEADS + h) * SEQ;
                *(float2*)&C[(base + s2) * HDIM + d]     = make_float2(c0, c1);
                *(float2*)&C[(base + s2 + 8) * HDIM + d] = make_float2(c2, c3);
            } else {
                // V -> transposed [B,H,D,S]; 8 qid lanes fill one 32B sector
                const size_t base = ((size_t)b * NHEADS + h) * HDIM;
                g_Vt[(base + d)     * SEQ + s2]     = c0;
                g_Vt[(base + d + 1) * SEQ + s2]     = c1;
                g_Vt[(base + d)     * SEQ + s2 + 8] = c2;
                g_Vt[(base + d + 1) * SEQ + s2 + 8] = c3;
            }
        }
    }
}

// ---------------------------------------------------------------------------
// Output projection GEMM — same NS=3 / one-barrier pipeline, plain epilogue.
// ---------------------------------------------------------------------------
__global__ __launch_bounds__(256, 2)
void gemm_out(const float* __restrict__ A, const float* __restrict__ B,
              const float* __restrict__ bias, float* __restrict__ C)
{
    extern __shared__ float smem[];
    constexpr int STF = 256 * SA;

    const int tid  = threadIdx.x;
    const int wid  = tid >> 5, lane = tid & 31;
    const int wm   = wid & 1, wn = wid >> 1;
    const int qid  = lane >> 2, tig = lane & 3;

    const float* gA = A + (size_t)(blockIdx.y * 128) * EMBED;
    const float* gB = B + (size_t)(blockIdx.x * 128) * EMBED;

    float acc[4][4][4] = {};

    auto loadStage = [&](int s, int k0) {
        float* sAp = smem + s * STF;
        float* sBp = sAp + 128 * SA;
        const int r0 = tid >> 3, c = (tid & 7) * 4;
        #pragma unroll
        for (int it = 0; it < 4; ++it) {
            const int r = r0 + it * 32;
            cp_async16(smem_u32(sAp + r * SA + c), gA + (size_t)r * EMBED + k0 + c);
        }
        #pragma unroll
        for (int it = 0; it < 4; ++it) {
            const int r = r0 + it * 32;
            cp_async16(smem_u32(sBp + r * SA + c), gB + (size_t)r * EMBED + k0 + c);
        }
        asm volatile("cp.async.commit_group;" ::: "memory");
    };

    const int ns = EMBED / 32;
    loadStage(0, 0);
    loadStage(1, 32);
    for (int i = 0; i < ns; ++i) {
        if (i + 1 < ns) {
            asm volatile("cp.async.wait_group 1;" ::: "memory");
        } else {
            asm volatile("cp.async.wait_group 0;" ::: "memory");
        }
        __syncthreads();
        if (i + 2 < ns) loadStage((i + 2) % 3, (i + 2) * 32);

        const float* sAp = smem + (i % 3) * STF;
        const float* sBp = sAp + 128 * SA;
        #pragma unroll
        for (int ks = 0; ks < 4; ++ks) {
            const int k = ks * 8 + tig;
            uint32_t af[4][4], bf[4][2];
            #pragma unroll
            for (int mt = 0; mt < 4; ++mt) {
                const float* ap = sAp + (wm * 64 + mt * 16 + qid) * SA + k;
                af[mt][0] = __float_as_uint(ap[0]);
                af[mt][1] = __float_as_uint(ap[8 * SA]);
                af[mt][2] = __float_as_uint(ap[4]);
                af[mt][3] = __float_as_uint(ap[8 * SA + 4]);
            }
            #pragma unroll
            for (int nt = 0; nt < 4; ++nt) {
                const float* bp = sBp + (wn * 32 + nt * 8 + qid) * SA + k;
                bf[nt][0] = __float_as_uint(bp[0]);
                bf[nt][1] = __float_as_uint(bp[4]);
            }
            #pragma unroll
            for (int mt = 0; mt < 4; ++mt)
                #pragma unroll
                for (int nt = 0; nt < 4; ++nt)
                    mma_tf32(acc[mt][nt], af[mt], bf[nt]);
        }
    }

    #pragma unroll
    for (int mt = 0; mt < 4; ++mt) {
        const int m = blockIdx.y * 128 + wm * 64 + mt * 16 + qid;
        #pragma unroll
        for (int nt = 0; nt < 4; ++nt) {
            const int n = blockIdx.x * 128 + wn * 32 + nt * 8 + tig * 2;
            const float b0 = bias[n], b1 = bias[n + 1];
            *(float2*)&C[(size_t)m * EMBED + n] =
                make_float2(acc[mt][nt][0] + b0, acc[mt][nt][1] + b1);
            *(float2*)&C[(size_t)(m + 8) * EMBED + n] =
                make_float2(acc[mt][nt][2] + b0, acc[mt][nt][3] + b1);
        }
    }
}

// ---------------------------------------------------------------------------
// Fused flash attention (R9 winner, unchanged): key-permuted K tile rows so
// the P·V A-frag is a register renaming of the softmaxed S C-frag.
// ---------------------------------------------------------------------------
__global__ __launch_bounds__(256, 2)
void k_flash(const float* __restrict__ Qg, const float* __restrict__ Kg,
             const float* __restrict__ Vtg, float* __restrict__ ctx)
{
    extern __shared__ float sm[];
    float* Qs = sm;                       // 128 x SQ8
    float* Ks = Qs + BQ * SQ8;            // 2 x 64 x SQ8   [key_perm][d]
    float* Vs = Ks + 2 * BKV * SQ8;       // 2 x 64 x SQ8   [d][key] natural

    const int tid = threadIdx.x;
    const int wid = tid >> 5, lane = tid & 31;
    const int qid = lane >> 2, tig = lane & 3;
    const int bh = blockIdx.z;
    const int b = bh >> 4, h = bh & 15;

    const float* gQ = Qg + ((size_t)bh * SEQ + blockIdx.x * BQ) * HDIM;
    const float* gK = Kg + (size_t)bh * SEQ * HDIM;
    const float* gV = Vtg + (size_t)bh * HDIM * SEQ;

    #pragma unroll
    for (int it = 0; it < 8; ++it) {
        int lin = tid + it * 256;
        int r = lin >> 4, c = (lin & 15) * 4;
        cp_async16(smem_u32(Qs + r * SQ8 + c), gQ + (size_t)r * HDIM + c);
    }
    asm volatile("cp.async.commit_group;" ::: "memory");

    auto loadKV = [&](int j, int buf) {
        float* kd = Ks + buf * BKV * SQ8;
        float* vd = Vs + buf * HDIM * SQ8;
        #pragma unroll
        for (int it = 0; it < 4; ++it) {
            int lin = tid + it * 256;
            int r = lin >> 4, c = (lin & 15) * 4;
            int rsrc = (r & ~7) | (((r & 7) >> 1) | ((r & 1) << 2));
            cp_async16(smem_u32(kd + r * SQ8 + c), gK + (size_t)(j * BKV + rsrc) * HDIM + c);
            cp_async16(smem_u32(vd + r * SQ8 + c), gV + (size_t)r * SEQ + j * BKV + c);
        }
        asm volatile("cp.async.commit_group;" ::: "memory");
    };

    loadKV(0, 0);

    float mrow0 = -1e30f, mrow1 = -1e30f;
    float lrow0 = 0.0f, lrow1 = 0.0f;
    float o[8][4] = {};
    const int rq = wid * 16 + qid;

    for (int j = 0; j < NJ; ++j) {
        if (j + 1 < NJ) {
            loadKV(j + 1, (j + 1) & 1);
            asm volatile("cp.async.wait_group 1;" ::: "memory");
        } else {
            asm volatile("cp.async.wait_group 0;" ::: "memory");
        }
        __syncthreads();

        float s[8][4] = {};
        const float* kb = Ks + (j & 1) * BKV * SQ8;
        #pragma unroll
        for (int ks = 0; ks < 8; ++ks) {
            const int k = ks * 8 + tig;
            uint32_t af[4];
            const float* ap = Qs + rq * SQ8 + k;
            af[0] = __float_as_uint(ap[0]);
            af[1] = __float_as_uint(ap[8 * SQ8]);
            af[2] = __float_as_uint(ap[4]);
            af[3] = __float_as_uint(ap[8 * SQ8 + 4]);
            #pragma unroll
            for (int nt = 0; nt < 8; ++nt) {
                const float* bp = kb + (nt * 8 + qid) * SQ8 + k;
                uint32_t bf[2] = {__float_as_uint(bp[0]), __float_as_uint(bp[4])};
                mma_tf32(s[nt], af, bf);
            }
        }

        float mx0 = -1e30f, mx1 = -1e30f;
        #pragma unroll
        for (int nt = 0; nt < 8; ++nt) {
            s[nt][0] *= SCALE_ATTN; s[nt][1] *= SCALE_ATTN;
            s[nt][2] *= SCALE_ATTN; s[nt][3] *= SCALE_ATTN;
            mx0 = fmaxf(mx0, fmaxf(s[nt][0], s[nt][1]));
            mx1 = fmaxf(mx1, fmaxf(s[nt][2], s[nt][3]));
        }
        mx0 = fmaxf(mx0, __shfl_xor_sync(0xffffffffu, mx0, 1));
        mx0 = fmaxf(mx0, __shfl_xor_sync(0xffffffffu, mx0, 2));
        mx1 = fmaxf(mx1, __shfl_xor_sync(0xffffffffu, mx1, 1));
        mx1 = fmaxf(mx1, __shfl_xor_sync(0xffffffffu, mx1, 2));
        const float mn0 = fmaxf(mrow0, mx0), mn1 = fmaxf(mrow1, mx1);
        const float a0 = __expf(mrow0 - mn0), a1 = __expf(mrow1 - mn1);
        mrow0 = mn0; mrow1 = mn1;

        float sum0 = 0.0f, sum1 = 0.0f;
        #pragma unroll
        for (int nt = 0; nt < 8; ++nt) {
            const float p0 = __expf(s[nt][0] - mn0), p1 = __expf(s[nt][1] - mn0);
            const float p2 = __expf(s[nt][2] - mn1), p3 = __expf(s[nt][3] - mn1);
            sum0 += p0 + p1; sum1 += p2 + p3;
            s[nt][0] = rna_tf32(p0); s[nt][1] = rna_tf32(p1);
            s[nt][2] = rna_tf32(p2); s[nt][3] = rna_tf32(p3);
        }
        sum0 += __shfl_xor_sync(0xffffffffu, sum0, 1);
        sum0 += __shfl_xor_sync(0xffffffffu, sum0, 2);
        sum1 += __shfl_xor_sync(0xffffffffu, sum1, 1);
        sum1 += __shfl_xor_sync(0xffffffffu, sum1, 2);
        lrow0 = lrow0 * a0 + sum0;
        lrow1 = lrow1 * a1 + sum1;
        #pragma unroll
        for (int nt = 0; nt < 8; ++nt) {
            o[nt][0] *= a0; o[nt][1] *= a0;
            o[nt][2] *= a1; o[nt][3] *= a1;
        }

        const float* vb = Vs + (j & 1) * HDIM * SQ8;
        #pragma unroll
        for (int kc = 0; kc < 8; ++kc) {
            uint32_t af[4];
            af[0] = __float_as_uint(s[kc][0]);
            af[1] = __float_as_uint(s[kc][2]);
            af[2] = __float_as_uint(s[kc][1]);
            af[3] = __float_as_uint(s[kc][3]);
            const int k = kc * 8 + tig;
            #pragma unroll
            for (int nt = 0; nt < 8; ++nt) {
                const float* bp = vb + (nt * 8 + qid) * SQ8 + k;
                uint32_t bf[2] = {__float_as_uint(bp[0]), __float_as_uint(bp[4])};
                mma_tf32(o[nt], af, bf);
            }
        }
        __syncthreads();
    }

    const float inv0 = 1.0f / lrow0, inv1 = 1.0f / lrow1;
    const int q0 = blockIdx.x * BQ + rq;
    float* dst0 = ctx + ((size_t)b * SEQ + q0) * EMBED + h * HDIM;
    float* dst1 = ctx + ((size_t)b * SEQ + q0 + 8) * EMBED + h * HDIM;
    #pragma unroll
    for (int nt = 0; nt < 8; ++nt) {
        const int d = nt * 8 + tig * 2;
        *(float2*)&dst0[d] = make_float2(rna_tf32(o[nt][0] * inv0),
                                         rna_tf32(o[nt][1] * inv0));
        *(float2*)&dst1[d] = make_float2(rna_tf32(o[nt][2] * inv1),
                                         rna_tf32(o[nt][3] * inv1));
    }
}

// ---------------------------------------------------------------------------
// Launch
// ---------------------------------------------------------------------------
#define SMEM_GEMM  (3 * 256 * SA * 4)                      // 110592 B (NS=3)
#define SMEM_FLASH ((BQ + 2 * BKV + 2 * HDIM) * SQ8 * 4)   // 104448 B -> 2 CTAs/SM

extern "C" void kernel_launch(void* const* d_in, const int* in_sizes, int n_in,
                              void* d_out, int out_size)
{
    (void)in_sizes; (void)n_in; (void)out_size;
    const float* query = (const float*)d_in[0];
    const float* key   = (const float*)d_in[1];
    const float* value = (const float*)d_in[2];
    const float* Wq = (const float*)d_in[3];  const float* bq = (const float*)d_in[4];
    const float* Wk = (const float*)d_in[5];  const float* bk = (const float*)d_in[6];
    const float* Wv = (const float*)d_in[7];  const float* bv = (const float*)d_in[8];
    const float* Wo = (const float*)d_in[9];  const float* bo = (const float*)d_in[10];
    float* out = (float*)d_out;

    float *Wdq, *QK, *Vt, *Cx;
    cudaGetSymbolAddress((void**)&Wdq, g_Wdq);
    cudaGetSymbolAddress((void**)&QK,  g_QK);
    cudaGetSymbolAddress((void**)&Vt,  g_Vt);
    cudaGetSymbolAddress((void**)&Cx,  g_ctx);

    cudaFuncSetAttribute(gemm_proj, cudaFuncAttributeMaxDynamicSharedMemorySize, SMEM_GEMM);
    cudaFuncSetAttribute(gemm_out,  cudaFuncAttributeMaxDynamicSharedMemorySize, SMEM_GEMM);
    cudaFuncSetAttribute(k_flash,   cudaFuncAttributeMaxDynamicSharedMemorySize, SMEM_FLASH);

    // 1) weight quant-dequant (+ tf32 RNA)
    k_reset<<<1, 32>>>();
    k_absmax<<<dim3(256, 4), 256>>>(Wq, Wk, Wv, Wo);
    k_dequant<<<dim3(WELEMS / (256 * 4), 4), 256>>>(Wq, Wk, Wv, Wo);

    // 2) fused Q/K/V projections (A rounded in-kernel; V written transposed)
    gemm_proj<<<dim3(EMBED / 128, TOKENS / 128, 3), 256, SMEM_GEMM>>>(
        query, key, value, bq, bk, bv);

    // 3) fused attention (QK^T + online softmax + PV) -> ctx [B,S,E]
    const size_t qkOff = (size_t)NBATCH * NHEADS * SEQ * HDIM;
    k_flash<<<dim3(SEQ / BQ, 1, NBATCH * NHEADS), 256, SMEM_FLASH>>>(
        QK, QK + qkOff, Vt, Cx);

    // 4) output projection -> d_out
    gemm_out<<<dim3(EMBED / 128, TOKENS / 128, 1), 256, SMEM_GEMM>>>(
        Cx, Wdq + 3 * (size_t)WELEMS, bo, out);
}

// round 13
// speedup vs baseline: 1.5443x; 1.5443x over previous
#include <cuda_runtime.h>
#include <cuda_fp16.h>
#include <cstdint>

// ---------------------------------------------------------------------------
// Problem constants
// ---------------------------------------------------------------------------
#define EMBED   1024
#define NHEADS  16
#define HDIM    64
#define NBATCH  2
#define SEQ     2048
#define TOKENS  (NBATCH * SEQ)          // 4096
#define WELEMS  (EMBED * EMBED)         // 1048576
#define SCALE_ATTN 0.125f               // 1/sqrt(64)
#define ST_H 40                         // GEMM smem row stride (fp16): 32 data + 8 pad
#define ST_F 72                         // FLASH smem row stride (fp16): 64 data + 8 pad (144B = 9*16B)

// Flash-attention tiling
#define BQ   128
#define BKV  64
#define NJ   (SEQ / BKV)                // 32

// ---------------------------------------------------------------------------
// Scratch (static __device__ globals; no runtime allocation allowed)
// ---------------------------------------------------------------------------
__device__ __half g_Wh[4 * WELEMS];                                   // fp16 dequant weights
__device__ int    g_absmax[4];
__device__ __half g_Xh[3 * (size_t)TOKENS * EMBED];                   // fp16 inputs
__device__ __half g_QKh[2 * (size_t)NBATCH * NHEADS * SEQ * HDIM];    // Q then K, [B,H,S,D]
__device__ __half g_Vth[(size_t)NBATCH * NHEADS * HDIM * SEQ];        // [B,H,D,S]
__device__ __half g_ctxh[(size_t)TOKENS * EMBED];                     // [B,S,E]

// ---------------------------------------------------------------------------
// Helpers (target-portable PTX only: mma.sync sm_80+, cp.async sm_80+)
// ---------------------------------------------------------------------------
__device__ __forceinline__ uint32_t smem_u32(const void* p) {
    uint32_t a;
    asm("{ .reg .u64 t; cvta.to.shared.u64 t, %1; cvt.u32.u64 %0, t; }" : "=r"(a) : "l"(p));
    return a;
}

__device__ __forceinline__ void cp_async16(uint32_t saddr, const void* gaddr) {
    asm volatile("cp.async.cg.shared.global [%0], [%1], 16;"
                 :: "r"(saddr), "l"(gaddr) : "memory");
}

// D(fp32x4) += A(fp16 4reg) * B(fp16 2reg)  — m16n8k16, sm_80-portable
__device__ __forceinline__ void mma_f16(float* d, const uint32_t* a, const uint32_t* b) {
    asm volatile(
        "mma.sync.aligned.m16n8k16.row.col.f32.f16.f16.f32 "
        "{%0,%1,%2,%3}, {%4,%5,%6,%7}, {%8,%9}, {%0,%1,%2,%3};"
        : "+f"(d[0]), "+f"(d[1]), "+f"(d[2]), "+f"(d[3])
        : "r"(a[0]), "r"(a[1]), "r"(a[2]), "r"(a[3]), "r"(b[0]), "r"(b[1]));
}

// pack two fp32 -> fp16x2 (lo = first arg), round-to-nearest
__device__ __forceinline__ uint32_t pack_h2(float lo, float hi) {
    uint32_t r;
    asm("cvt.rn.f16x2.f32 %0, %1, %2;" : "=r"(r) : "f"(hi), "f"(lo));
    return r;
}

// ---------------------------------------------------------------------------
// Weight quantization (bit-faithful: s = max|W|/127, round-half-even, clip,
// dequantize), output stored fp16 RN (same 10-bit mantissa as tf32 path).
// ---------------------------------------------------------------------------
__global__ void k_reset() { if (threadIdx.x < 4) g_absmax[threadIdx.x] = 0; }

__global__ void k_absmax(const float* __restrict__ w0, const float* __restrict__ w1,
                         const float* __restrict__ w2, const float* __restrict__ w3)
{
    const float* W = (blockIdx.y == 0) ? w0 : (blockIdx.y == 1) ? w1
                   : (blockIdx.y == 2) ? w2 : w3;
    float m = 0.0f;
    for (int i = blockIdx.x * blockDim.x + threadIdx.x; i < WELEMS;
         i += gridDim.x * blockDim.x)
        m = fmaxf(m, fabsf(W[i]));
    #pragma unroll
    for (int o = 16; o; o >>= 1) m = fmaxf(m, __shfl_xor_sync(0xffffffffu, m, o));
    if ((threadIdx.x & 31) == 0) atomicMax(&g_absmax[blockIdx.y], __float_as_int(m));
}

__global__ void k_dequant(const float* __restrict__ w0, const float* __restrict__ w1,
                          const float* __restrict__ w2, const float* __restrict__ w3)
{
    int sel = blockIdx.y;
    const float* W = (sel == 0) ? w0 : (sel == 1) ? w1 : (sel == 2) ? w2 : w3;
    float s = __int_as_float(g_absmax[sel]) / 127.0f;
    int i = (blockIdx.x * blockDim.x + threadIdx.x) * 4;
    float4 w = *(const float4*)&W[i];
    __half2 h0 = __floats2half2_rn(
        fminf(fmaxf(rintf(w.x / s), -128.0f), 127.0f) * s,
        fminf(fmaxf(rintf(w.y / s), -128.0f), 127.0f) * s);
    __half2 h1 = __floats2half2_rn(
        fminf(fmaxf(rintf(w.z / s), -128.0f), 127.0f) * s,
        fminf(fmaxf(rintf(w.w / s), -128.0f), 127.0f) * s);
    *(__half2*)&g_Wh[(size_t)sel * WELEMS + i]     = h0;
    *(__half2*)&g_Wh[(size_t)sel * WELEMS + i + 2] = h1;
}

// inputs fp32 -> fp16 copies
__global__ void k_cvt_h(const float* __restrict__ q, const float* __restrict__ k,
                        const float* __restrict__ v)
{
    int sel = blockIdx.y;
    const float* s = (sel == 0) ? q : (sel == 1) ? k : v;
    __half* d = g_Xh + (size_t)sel * TOKENS * EMBED;
    int i = (blockIdx.x * blockDim.x + threadIdx.x) * 4;
    float4 w = *(const float4*)&s[i];
    *(__half2*)&d[i]     = __floats2half2_rn(w.x, w.y);
    *(__half2*)&d[i + 2] = __floats2half2_rn(w.z, w.w);
}

// ---------------------------------------------------------------------------
// fp16 NT GEMM mainloop (m16n8k16): C[128x128] = A[128,K] * B[128,K]^T,
// K tiled by 32, NS=3 cp.async. Row stride ST_H=40 (32 data + 8 pad):
// fragment banks (20*qid + 8ks + tig) mod 32 all-distinct -> conflict-free.
// ---------------------------------------------------------------------------
#define GEMM_MAINLOOP(sAbase, GA, GB, ACC)                                       \
    auto loadStage = [&](int st, int k0) {                                       \
        __half* sAp = (sAbase) + st * (256 * ST_H);                              \
        __half* sBp = sAp + 128 * ST_H;                                          \
        const int r0 = tid >> 2, c = (tid & 3) * 8;                              \
        _Pragma("unroll")                                                        \
        for (int it = 0; it < 2; ++it) {                                         \
            const int r = r0 + it * 64;                                          \
            cp_async16(smem_u32(sAp + r * ST_H + c), (GA) + (size_t)r * EMBED + k0 + c); \
        }                                                                        \
        _Pragma("unroll")                                                        \
        for (int it = 0; it < 2; ++it) {                                         \
            const int r = r0 + it * 64;                                          \
            cp_async16(smem_u32(sBp + r * ST_H + c), (GB) + (size_t)r * EMBED + k0 + c); \
        }                                                                        \
        asm volatile("cp.async.commit_group;" ::: "memory");                     \
    };                                                                           \
    const int ns = EMBED / 32;                                                   \
    loadStage(0, 0);                                                             \
    loadStage(1, 32);                                                            \
    for (int i = 0; i < ns; ++i) {                                               \
        if (i + 1 < ns) { asm volatile("cp.async.wait_group 1;" ::: "memory"); } \
        else            { asm volatile("cp.async.wait_group 0;" ::: "memory"); } \
        __syncthreads();                                                         \
        if (i + 2 < ns) loadStage((i + 2) % 3, (i + 2) * 32);                    \
        const __half* sAp = (sAbase) + (i % 3) * (256 * ST_H);                   \
        const __half* sBp = sAp + 128 * ST_H;                                    \
        _Pragma("unroll")                                                        \
        for (int ks = 0; ks < 2; ++ks) {                                         \
            const int kb = ks * 16 + 2 * tig;                                    \
            uint32_t af[4][4], bf[4][2];                                         \
            _Pragma("unroll")                                                    \
            for (int mt = 0; mt < 4; ++mt) {                                     \
                const __half* ap = sAp + (wm * 64 + mt * 16 + qid) * ST_H + kb;  \
                af[mt][0] = *(const uint32_t*)(ap);                              \
                af[mt][1] = *(const uint32_t*)(ap + 8 * ST_H);                   \
                af[mt][2] = *(const uint32_t*)(ap + 8);                          \
                af[mt][3] = *(const uint32_t*)(ap + 8 * ST_H + 8);               \
            }                                                                    \
            _Pragma("unroll")                                                    \
            for (int nt = 0; nt < 4; ++nt) {                                     \
                const __half* bp = sBp + (wn * 32 + nt * 8 + qid) * ST_H + kb;   \
                bf[nt][0] = *(const uint32_t*)(bp);                              \
                bf[nt][1] = *(const uint32_t*)(bp + 8);                          \
            }                                                                    \
            _Pragma("unroll")                                                    \
            for (int mt = 0; mt < 4; ++mt)                                       \
                _Pragma("unroll")                                                \
                for (int nt = 0; nt < 4; ++nt)                                   \
                    mma_f16(ACC[mt][nt], af[mt], bf[nt]);                        \
        }                                                                        \
    }

// ---------------------------------------------------------------------------
// Fused Q/K/V projection (grid z in {0,1,2}); fp16 in, fp16 out.
// z<2: [B,H,S,D] half2 stores; z==2: V -> [B,H,D,S] scalar half stores.
// ---------------------------------------------------------------------------
__global__ __launch_bounds__(256, 2)
void gemm_proj(const float* __restrict__ b0, const float* __restrict__ b1,
               const float* __restrict__ b2)
{
    extern __shared__ __half smem[];
    const int tid  = threadIdx.x;
    const int wid  = tid >> 5, lane = tid & 31;
    const int wm   = wid & 1, wn = wid >> 1;
    const int qid  = lane >> 2, tig = lane & 3;
    const int z    = blockIdx.z;

    const float* bias = (z == 0) ? b0 : (z == 1) ? b1 : b2;
    const __half* gA = g_Xh + (size_t)z * TOKENS * EMBED + (size_t)(blockIdx.y * 128) * EMBED;
    const __half* gB = g_Wh + (size_t)z * WELEMS + (size_t)(blockIdx.x * 128) * EMBED;

    float acc[4][4][4] = {};
    GEMM_MAINLOOP(smem, gA, gB, acc)

    #pragma unroll
    for (int mt = 0; mt < 4; ++mt) {
        const int m = blockIdx.y * 128 + wm * 64 + mt * 16 + qid;
        const int b = m >> 11, s2 = m & (SEQ - 1);
        #pragma unroll
        for (int nt = 0; nt < 4; ++nt) {
            const int n = blockIdx.x * 128 + wn * 32 + nt * 8 + tig * 2;
            const int h = n >> 6, d = n & (HDIM - 1);
            const float bb0 = bias[n], bb1 = bias[n + 1];
            const float c0 = acc[mt][nt][0] + bb0, c1 = acc[mt][nt][1] + bb1;
            const float c2 = acc[mt][nt][2] + bb0, c3 = acc[mt][nt][3] + bb1;
            if (z < 2) {
                __half* C = g_QKh + (size_t)z * ((size_t)NBATCH * NHEADS * SEQ * HDIM);
                const size_t base = ((size_t)b * NHEADS + h) * SEQ;
                *(uint32_t*)&C[(base + s2) * HDIM + d]     = pack_h2(c0, c1);
                *(uint32_t*)&C[(base + s2 + 8) * HDIM + d] = pack_h2(c2, c3);
            } else {
                const size_t base = ((size_t)b * NHEADS + h) * HDIM;
                g_Vth[(base + d)     * SEQ + s2]     = __float2half_rn(c0);
                g_Vth[(base + d + 1) * SEQ + s2]     = __float2half_rn(c1);
                g_Vth[(base + d)     * SEQ + s2 + 8] = __float2half_rn(c2);
                g_Vth[(base + d + 1) * SEQ + s2 + 8] = __float2half_rn(c3);
            }
        }
    }
}

// ---------------------------------------------------------------------------
// Output projection: fp16 operands, fp32 result to d_out.
// ---------------------------------------------------------------------------
__global__ __launch_bounds__(256, 2)
void gemm_out(const float* __restrict__ bias, float* __restrict__ C)
{
    extern __shared__ __half smem[];
    const int tid  = threadIdx.x;
    const int wid  = tid >> 5, lane = tid & 31;
    const int wm   = wid & 1, wn = wid >> 1;
    const int qid  = lane >> 2, tig = lane & 3;

    const __half* gA = g_ctxh + (size_t)(blockIdx.y * 128) * EMBED;
    const __half* gB = g_Wh + 3 * (size_t)WELEMS + (size_t)(blockIdx.x * 128) * EMBED;

    float acc[4][4][4] = {};
    GEMM_MAINLOOP(smem, gA, gB, acc)

    #pragma unroll
    for (int mt = 0; mt < 4; ++mt) {
        const int m = blockIdx.y * 128 + wm * 64 + mt * 16 + qid;
        #pragma unroll
        for (int nt = 0; nt < 4; ++nt) {
            const int n = blockIdx.x * 128 + wn * 32 + nt * 8 + tig * 2;
            const float b0 = bias[n], b1 = bias[n + 1];
            *(float2*)&C[(size_t)m * EMBED + n] =
                make_float2(acc[mt][nt][0] + b0, acc[mt][nt][1] + b1);
            *(float2*)&C[(size_t)(m + 8) * EMBED + n] =
                make_float2(acc[mt][nt][2] + b0, acc[mt][nt][3] + b1);
        }
    }
}

// ---------------------------------------------------------------------------
// Fused flash attention, fp16 operands (m16n8k16), row stride ST_F=72
// (64 data halves + 8 pad; 144B rows, 16B-aligned chunks).
// Fragment banks: (36*row + 8ks + tig) mod 32 -> (4*qid + tig + 8ks) mod 32,
// all 32 lanes distinct -> conflict-free.
// S C-frag packs DIRECTLY into the PV A-frag (pack_h2 of c-pairs).
// ---------------------------------------------------------------------------
__global__ __launch_bounds__(256, 2)
void k_flash(const __half* __restrict__ Qg, const __half* __restrict__ Kg,
             const __half* __restrict__ Vtg, __half* __restrict__ ctx)
{
    extern __shared__ __half sm[];
    __half* Qs = sm;                         // 128 x ST_F
    __half* Ks = Qs + BQ * ST_F;             // 2 x 64 x ST_F  [key][d]
    __half* Vs = Ks + 2 * BKV * ST_F;        // 2 x 64 x ST_F  [d][key]

    const int tid = threadIdx.x;
    const int wid = tid >> 5, lane = tid & 31;
    const int qid = lane >> 2, tig = lane & 3;
    const int bh = blockIdx.z;
    const int b = bh >> 4, h = bh & 15;

    const __half* gQ = Qg + ((size_t)bh * SEQ + blockIdx.x * BQ) * HDIM;
    const __half* gK = Kg + (size_t)bh * SEQ * HDIM;
    const __half* gV = Vtg + (size_t)bh * HDIM * SEQ;

    // Q tile: 128 rows x 64 fp16 (128 B) = 1024 16B-chunks
    #pragma unroll
    for (int it = 0; it < 4; ++it) {
        int lin = tid + it * 256;
        int r = lin >> 3, c = (lin & 7) * 8;
        cp_async16(smem_u32(Qs + r * ST_F + c), gQ + (size_t)r * HDIM + c);
    }
    asm volatile("cp.async.commit_group;" ::: "memory");

    auto loadKV = [&](int j, int buf) {
        __half* kd = Ks + buf * BKV * ST_F;
        __half* vd = Vs + buf * HDIM * ST_F;
        #pragma unroll
        for (int it = 0; it < 2; ++it) {
            int lin = tid + it * 256;
            int r = lin >> 3, c = (lin & 7) * 8;
            cp_async16(smem_u32(kd + r * ST_F + c), gK + (size_t)(j * BKV + r) * HDIM + c);
            cp_async16(smem_u32(vd + r * ST_F + c), gV + (size_t)r * SEQ + j * BKV + c);
        }
        asm volatile("cp.async.commit_group;" ::: "memory");
    };

    loadKV(0, 0);

    float mrow0 = -1e30f, mrow1 = -1e30f;
    float lrow0 = 0.0f, lrow1 = 0.0f;
    float o[8][4] = {};
    const int rq = wid * 16 + qid;

    for (int j = 0; j < NJ; ++j) {
        if (j + 1 < NJ) {
            loadKV(j + 1, (j + 1) & 1);
            asm volatile("cp.async.wait_group 1;" ::: "memory");
        } else {
            asm volatile("cp.async.wait_group 0;" ::: "memory");
        }
        __syncthreads();

        // ---- S = Q K^T  (16 q rows x 64 keys; 4 k16 chunks over d) ----
        float s[8][4] = {};
        const __half* kb = Ks + (j & 1) * BKV * ST_F;
        #pragma unroll
        for (int ks = 0; ks < 4; ++ks) {
            const int kb2 = ks * 16 + 2 * tig;
            uint32_t af[4];
            const __half* ap = Qs + rq * ST_F + kb2;
            af[0] = *(const uint32_t*)(ap);
            af[1] = *(const uint32_t*)(ap + 8 * ST_F);
            af[2] = *(const uint32_t*)(ap + 8);
            af[3] = *(const uint32_t*)(ap + 8 * ST_F + 8);
            #pragma unroll
            for (int nt = 0; nt < 8; ++nt) {
                const __half* bp = kb + (nt * 8 + qid) * ST_F + kb2;
                uint32_t bf[2] = {*(const uint32_t*)(bp), *(const uint32_t*)(bp + 8)};
                mma_f16(s[nt], af, bf);
            }
        }

        // ---- online softmax (rows rq, rq+8); keys in natural order ----
        float mx0 = -1e30f, mx1 = -1e30f;
        #pragma unroll
        for (int nt = 0; nt < 8; ++nt) {
            s[nt][0] *= SCALE_ATTN; s[nt][1] *= SCALE_ATTN;
            s[nt][2] *= SCALE_ATTN; s[nt][3] *= SCALE_ATTN;
            mx0 = fmaxf(mx0, fmaxf(s[nt][0], s[nt][1]));
            mx1 = fmaxf(mx1, fmaxf(s[nt][2], s[nt][3]));
        }
        mx0 = fmaxf(mx0, __shfl_xor_sync(0xffffffffu, mx0, 1));
        mx0 = fmaxf(mx0, __shfl_xor_sync(0xffffffffu, mx0, 2));
        mx1 = fmaxf(mx1, __shfl_xor_sync(0xffffffffu, mx1, 1));
        mx1 = fmaxf(mx1, __shfl_xor_sync(0xffffffffu, mx1, 2));
        const float mn0 = fmaxf(mrow0, mx0), mn1 = fmaxf(mrow1, mx1);
        const float a0 = __expf(mrow0 - mn0), a1 = __expf(mrow1 - mn1);
        mrow0 = mn0; mrow1 = mn1;

        float sum0 = 0.0f, sum1 = 0.0f;
        #pragma unroll
        for (int nt = 0; nt < 8; ++nt) {
            s[nt][0] = __expf(s[nt][0] - mn0); s[nt][1] = __expf(s[nt][1] - mn0);
            s[nt][2] = __expf(s[nt][2] - mn1); s[nt][3] = __expf(s[nt][3] - mn1);
            sum0 += s[nt][0] + s[nt][1]; sum1 += s[nt][2] + s[nt][3];
        }
        sum0 += __shfl_xor_sync(0xffffffffu, sum0, 1);
        sum0 += __shfl_xor_sync(0xffffffffu, sum0, 2);
        sum1 += __shfl_xor_sync(0xffffffffu, sum1, 1);
        sum1 += __shfl_xor_sync(0xffffffffu, sum1, 2);
        lrow0 = lrow0 * a0 + sum0;
        lrow1 = lrow1 * a1 + sum1;
        #pragma unroll
        for (int nt = 0; nt < 8; ++nt) {
            o[nt][0] *= a0; o[nt][1] *= a0;
            o[nt][2] *= a1; o[nt][3] *= a1;
        }

        // ---- O += P V : A-frag = packed C-frags; B = V^T fp16 ----
        const __half* vb = Vs + (j & 1) * HDIM * ST_F;
        #pragma unroll
        for (int kc = 0; kc < 4; ++kc) {       // keys 16kc .. 16kc+15
            uint32_t af[4];
            af[0] = pack_h2(s[2 * kc][0],     s[2 * kc][1]);
            af[1] = pack_h2(s[2 * kc][2],     s[2 * kc][3]);
            af[2] = pack_h2(s[2 * kc + 1][0], s[2 * kc + 1][1]);
            af[3] = pack_h2(s[2 * kc + 1][2], s[2 * kc + 1][3]);
            const int key2 = kc * 16 + 2 * tig;
            #pragma unroll
            for (int nt = 0; nt < 8; ++nt) {
                const __half* bp = vb + (nt * 8 + qid) * ST_F + key2;
                uint32_t bf[2] = {*(const uint32_t*)(bp), *(const uint32_t*)(bp + 8)};
                mma_f16(o[nt], af, bf);
            }
        }
        __syncthreads();
    }

    // ---- epilogue: O /= l, fp16 RN, write ctx [B,S,E] ----
    const float inv0 = 1.0f / lrow0, inv1 = 1.0f / lrow1;
    const int q0 = blockIdx.x * BQ + rq;
    __half* dst0 = ctx + ((size_t)b * SEQ + q0) * EMBED + h * HDIM;
    __half* dst1 = ctx + ((size_t)b * SEQ + q0 + 8) * EMBED + h * HDIM;
    #pragma unroll
    for (int nt = 0; nt < 8; ++nt) {
        const int d = nt * 8 + tig * 2;
        *(uint32_t*)&dst0[d] = pack_h2(o[nt][0] * inv0, o[nt][1] * inv0);
        *(uint32_t*)&dst1[d] = pack_h2(o[nt][2] * inv1, o[nt][3] * inv1);
    }
}

// ---------------------------------------------------------------------------
// Launch
// ---------------------------------------------------------------------------
#define SMEM_GEMM  (3 * 256 * ST_H * 2)                    // 61440 B (NS=3, fp16)
#define SMEM_FLASH ((BQ + 2 * BKV + 2 * HDIM) * ST_F * 2)  // 55296 B

extern "C" void kernel_launch(void* const* d_in, const int* in_sizes, int n_in,
                              void* d_out, int out_size)
{
    (void)in_sizes; (void)n_in; (void)out_size;
    const float* query = (const float*)d_in[0];
    const float* key   = (const float*)d_in[1];
    const float* value = (const float*)d_in[2];
    const float* Wq = (const float*)d_in[3];  const float* bq = (const float*)d_in[4];
    const float* Wk = (const float*)d_in[5];  const float* bk = (const float*)d_in[6];
    const float* Wv = (const float*)d_in[7];  const float* bv = (const float*)d_in[8];
    const float* Wo = (const float*)d_in[9];  const float* bo = (const float*)d_in[10];
    float* out = (float*)d_out;

    __half *QKh, *Vth, *Cxh;
    cudaGetSymbolAddress((void**)&QKh, g_QKh);
    cudaGetSymbolAddress((void**)&Vth, g_Vth);
    cudaGetSymbolAddress((void**)&Cxh, g_ctxh);

    cudaFuncSetAttribute(gemm_proj, cudaFuncAttributeMaxDynamicSharedMemorySize, SMEM_GEMM);
    cudaFuncSetAttribute(gemm_out,  cudaFuncAttributeMaxDynamicSharedMemorySize, SMEM_GEMM);
    cudaFuncSetAttribute(k_flash,   cudaFuncAttributeMaxDynamicSharedMemorySize, SMEM_FLASH);

    // 1) weight quant-dequant -> fp16; inputs -> fp16
    k_reset<<<1, 32>>>();
    k_absmax<<<dim3(256, 4), 256>>>(Wq, Wk, Wv, Wo);
    k_dequant<<<dim3(WELEMS / (256 * 4), 4), 256>>>(Wq, Wk, Wv, Wo);
    k_cvt_h<<<dim3(TOKENS * EMBED / (256 * 4), 3), 256>>>(query, key, value);

    // 2) fused Q/K/V projections (V written transposed)
    gemm_proj<<<dim3(EMBED / 128, TOKENS / 128, 3), 256, SMEM_GEMM>>>(bq, bk, bv);

    // 3) fused attention -> ctx fp16 [B,S,E]
    const size_t qkOff = (size_t)NBATCH * NHEADS * SEQ * HDIM;
    k_flash<<<dim3(SEQ / BQ, 1, NBATCH * NHEADS), 256, SMEM_FLASH>>>(
        QKh, QKh + qkOff, Vth, Cxh);

    // 4) output projection -> d_out (fp32)
    gemm_out<<<dim3(EMBED / 128, TOKENS / 128, 1), 256, SMEM_GEMM>>>(bo, out);
}

// round 14
// speedup vs baseline: 1.7018x; 1.1019x over previous
#include <cuda_runtime.h>
#include <cuda_fp16.h>
#include <cstdint>

// ---------------------------------------------------------------------------
// Problem constants
// ---------------------------------------------------------------------------
#define EMBED   1024
#define NHEADS  16
#define HDIM    64
#define NBATCH  2
#define SEQ     2048
#define TOKENS  (NBATCH * SEQ)          // 4096
#define WELEMS  (EMBED * EMBED)         // 1048576
#define SCALE_ATTN 0.125f               // 1/sqrt(64)
#define ST_H 40                         // GEMM smem row stride (fp16): 32 data + 8 pad
#define ST_F 72                         // FLASH smem row stride (fp16): 64 data + 8 pad

// Flash-attention tiling
#define BQ   128
#define BKV  64
#define NJ   (SEQ / BKV)                // 32

// ---------------------------------------------------------------------------
// Scratch (static __device__ globals; no runtime allocation allowed)
// ---------------------------------------------------------------------------
__device__ __half g_Wh[4 * WELEMS];                                   // fp16 dequant weights
__device__ int    g_absmax[4];
__device__ __half g_Xh[3 * (size_t)TOKENS * EMBED];                   // fp16 inputs
__device__ __half g_QKh[2 * (size_t)NBATCH * NHEADS * SEQ * HDIM];    // Q then K, [B,H,S,D]
__device__ __half g_Vth[(size_t)NBATCH * NHEADS * HDIM * SEQ];        // [B,H,D,S]
__device__ __half g_ctxh[(size_t)TOKENS * EMBED];                     // [B,S,E]

// ---------------------------------------------------------------------------
// Helpers (target-portable: mma.sync sm_80+, cp.async sm_80+, ldmatrix sm_75+)
// ---------------------------------------------------------------------------
__device__ __forceinline__ uint32_t smem_u32(const void* p) {
    uint32_t a;
    asm("{ .reg .u64 t; cvta.to.shared.u64 t, %1; cvt.u32.u64 %0, t; }" : "=r"(a) : "l"(p));
    return a;
}

__device__ __forceinline__ void cp_async16(uint32_t saddr, const void* gaddr) {
    asm volatile("cp.async.cg.shared.global [%0], [%1], 16;"
                 :: "r"(saddr), "l"(gaddr) : "memory");
}

// D(fp32x4) += A(fp16 4reg) * B(fp16 2reg)  — m16n8k16
__device__ __forceinline__ void mma_f16(float* d, const uint32_t* a, const uint32_t* b) {
    asm volatile(
        "mma.sync.aligned.m16n8k16.row.col.f32.f16.f16.f32 "
        "{%0,%1,%2,%3}, {%4,%5,%6,%7}, {%8,%9}, {%0,%1,%2,%3};"
        : "+f"(d[0]), "+f"(d[1]), "+f"(d[2]), "+f"(d[3])
        : "r"(a[0]), "r"(a[1]), "r"(a[2]), "r"(a[3]), "r"(b[0]), "r"(b[1]));
}

__device__ __forceinline__ void ldsm_x4(uint32_t* r, uint32_t addr) {
    asm volatile("ldmatrix.sync.aligned.m8n8.x4.shared.b16 {%0,%1,%2,%3}, [%4];"
                 : "=r"(r[0]), "=r"(r[1]), "=r"(r[2]), "=r"(r[3]) : "r"(addr));
}

// pack two fp32 -> fp16x2 (lo = first arg), round-to-nearest
__device__ __forceinline__ uint32_t pack_h2(float lo, float hi) {
    uint32_t r;
    asm("cvt.rn.f16x2.f32 %0, %1, %2;" : "=r"(r) : "f"(hi), "f"(lo));
    return r;
}

// ---------------------------------------------------------------------------
// Weight quantization (bit-faithful) -> fp16; inputs -> fp16
// ---------------------------------------------------------------------------
__global__ void k_reset() { if (threadIdx.x < 4) g_absmax[threadIdx.x] = 0; }

__global__ void k_absmax(const float* __restrict__ w0, const float* __restrict__ w1,
                         const float* __restrict__ w2, const float* __restrict__ w3)
{
    const float* W = (blockIdx.y == 0) ? w0 : (blockIdx.y == 1) ? w1
                   : (blockIdx.y == 2) ? w2 : w3;
    float m = 0.0f;
    for (int i = blockIdx.x * blockDim.x + threadIdx.x; i < WELEMS;
         i += gridDim.x * blockDim.x)
        m = fmaxf(m, fabsf(W[i]));
    #pragma unroll
    for (int o = 16; o; o >>= 1) m = fmaxf(m, __shfl_xor_sync(0xffffffffu, m, o));
    if ((threadIdx.x & 31) == 0) atomicMax(&g_absmax[blockIdx.y], __float_as_int(m));
}

__global__ void k_dequant(const float* __restrict__ w0, const float* __restrict__ w1,
                          const float* __restrict__ w2, const float* __restrict__ w3)
{
    int sel = blockIdx.y;
    const float* W = (sel == 0) ? w0 : (sel == 1) ? w1 : (sel == 2) ? w2 : w3;
    float s = __int_as_float(g_absmax[sel]) / 127.0f;
    int i = (blockIdx.x * blockDim.x + threadIdx.x) * 4;
    float4 w = *(const float4*)&W[i];
    __half2 h0 = __floats2half2_rn(
        fminf(fmaxf(rintf(w.x / s), -128.0f), 127.0f) * s,
        fminf(fmaxf(rintf(w.y / s), -128.0f), 127.0f) * s);
    __half2 h1 = __floats2half2_rn(
        fminf(fmaxf(rintf(w.z / s), -128.0f), 127.0f) * s,
        fminf(fmaxf(rintf(w.w / s), -128.0f), 127.0f) * s);
    *(__half2*)&g_Wh[(size_t)sel * WELEMS + i]     = h0;
    *(__half2*)&g_Wh[(size_t)sel * WELEMS + i + 2] = h1;
}

__global__ void k_cvt_h(const float* __restrict__ q, const float* __restrict__ k,
                        const float* __restrict__ v)
{
    int sel = blockIdx.y;
    const float* s = (sel == 0) ? q : (sel == 1) ? k : v;
    __half* d = g_Xh + (size_t)sel * TOKENS * EMBED;
    int i = (blockIdx.x * blockDim.x + threadIdx.x) * 4;
    float4 w = *(const float4*)&s[i];
    *(__half2*)&d[i]     = __floats2half2_rn(w.x, w.y);
    *(__half2*)&d[i + 2] = __floats2half2_rn(w.z, w.w);
}

// ---------------------------------------------------------------------------
// fp16 NT GEMM mainloop (m16n8k16), NS=3 cp.async, ldmatrix fragments.
// ldmatrix lane maps (canonical sm80):
//   A 16x16 x4: row base+(lane&15), col (lane>>4)*8  -> {a0,a1,a2,a3}
//   B two n8  : row (lane&7)+((lane>>4)<<3), col ((lane>>3)&1)*8
//               -> {b(nt)[0], b(nt)[1], b(nt+1)[0], b(nt+1)[1]}
// Banks: row stride 80B -> start bank 20r mod 32 covers all 32 -> conflict-free.
// ---------------------------------------------------------------------------
#define GEMM_MAINLOOP(SMEMU, GA, GB, ACC)                                        \
    const uint32_t aOff = ((wm * 64 + (lane & 15)) * ST_H + (lane >> 4) * 8) * 2;\
    const uint32_t bOff = ((wn * 32 + (lane & 7) + ((lane >> 4) << 3)) * ST_H    \
                           + ((lane >> 3) & 1) * 8) * 2;                         \
    auto loadStage = [&](int st, int k0) {                                       \
        uint32_t sAp = (SMEMU) + st * (256 * ST_H * 2);                          \
        uint32_t sBp = sAp + 128 * ST_H * 2;                                     \
        const int r0 = tid >> 2, c = (tid & 3) * 8;                              \
        _Pragma("unroll")                                                        \
        for (int it = 0; it < 2; ++it) {                                         \
            const int r = r0 + it * 64;                                          \
            cp_async16(sAp + (r * ST_H + c) * 2, (GA) + (size_t)r * EMBED + k0 + c); \
        }                                                                        \
        _Pragma("unroll")                                                        \
        for (int it = 0; it < 2; ++it) {                                         \
            const int r = r0 + it * 64;                                          \
            cp_async16(sBp + (r * ST_H + c) * 2, (GB) + (size_t)r * EMBED + k0 + c); \
        }                                                                        \
        asm volatile("cp.async.commit_group;" ::: "memory");                     \
    };                                                                           \
    const int ns = EMBED / 32;                                                   \
    loadStage(0, 0);                                                             \
    loadStage(1, 32);                                                            \
    for (int i = 0; i < ns; ++i) {                                               \
        if (i + 1 < ns) { asm volatile("cp.async.wait_group 1;" ::: "memory"); } \
        else            { asm volatile("cp.async.wait_group 0;" ::: "memory"); } \
        __syncthreads();                                                         \
        if (i + 2 < ns) loadStage((i + 2) % 3, (i + 2) * 32);                    \
        const uint32_t aBase = (SMEMU) + (i % 3) * (256 * ST_H * 2) + aOff;      \
        const uint32_t bBase = (SMEMU) + (i % 3) * (256 * ST_H * 2)              \
                               + 128 * ST_H * 2 + bOff;                          \
        _Pragma("unroll")                                                        \
        for (int ks = 0; ks < 2; ++ks) {                                         \
            uint32_t af[4][4], bq[2][4];                                         \
            _Pragma("unroll")                                                    \
            for (int mt = 0; mt < 4; ++mt)                                       \
                ldsm_x4(af[mt], aBase + mt * (16 * ST_H * 2) + ks * 32);         \
            _Pragma("unroll")                                                    \
            for (int np = 0; np < 2; ++np)                                       \
                ldsm_x4(bq[np], bBase + np * (16 * ST_H * 2) + ks * 32);         \
            _Pragma("unroll")                                                    \
            for (int mt = 0; mt < 4; ++mt)                                       \
                _Pragma("unroll")                                                \
                for (int nt = 0; nt < 4; ++nt)                                   \
                    mma_f16(ACC[mt][nt], af[mt], &bq[nt >> 1][(nt & 1) * 2]);    \
        }                                                                        \
    }

// ---------------------------------------------------------------------------
// Fused Q/K/V projection (grid z in {0,1,2}); fp16 in, fp16 out.
// ---------------------------------------------------------------------------
__global__ __launch_bounds__(256, 2)
void gemm_proj(const float* __restrict__ b0, const float* __restrict__ b1,
               const float* __restrict__ b2)
{
    extern __shared__ __half smem[];
    const uint32_t smemU = smem_u32(smem);
    const int tid  = threadIdx.x;
    const int wid  = tid >> 5, lane = tid & 31;
    const int wm   = wid & 1, wn = wid >> 1;
    const int qid  = lane >> 2, tig = lane & 3;
    const int z    = blockIdx.z;

    const float* bias = (z == 0) ? b0 : (z == 1) ? b1 : b2;
    const __half* gA = g_Xh + (size_t)z * TOKENS * EMBED + (size_t)(blockIdx.y * 128) * EMBED;
    const __half* gB = g_Wh + (size_t)z * WELEMS + (size_t)(blockIdx.x * 128) * EMBED;

    float acc[4][4][4] = {};
    GEMM_MAINLOOP(smemU, gA, gB, acc)

    #pragma unroll
    for (int mt = 0; mt < 4; ++mt) {
        const int m = blockIdx.y * 128 + wm * 64 + mt * 16 + qid;
        const int b = m >> 11, s2 = m & (SEQ - 1);
        #pragma unroll
        for (int nt = 0; nt < 4; ++nt) {
            const int n = blockIdx.x * 128 + wn * 32 + nt * 8 + tig * 2;
            const int h = n >> 6, d = n & (HDIM - 1);
            const float bb0 = bias[n], bb1 = bias[n + 1];
            const float c0 = acc[mt][nt][0] + bb0, c1 = acc[mt][nt][1] + bb1;
            const float c2 = acc[mt][nt][2] + bb0, c3 = acc[mt][nt][3] + bb1;
            if (z < 2) {
                __half* C = g_QKh + (size_t)z * ((size_t)NBATCH * NHEADS * SEQ * HDIM);
                const size_t base = ((size_t)b * NHEADS + h) * SEQ;
                *(uint32_t*)&C[(base + s2) * HDIM + d]     = pack_h2(c0, c1);
                *(uint32_t*)&C[(base + s2 + 8) * HDIM + d] = pack_h2(c2, c3);
            } else {
                const size_t base = ((size_t)b * NHEADS + h) * HDIM;
                g_Vth[(base + d)     * SEQ + s2]     = __float2half_rn(c0);
                g_Vth[(base + d + 1) * SEQ + s2]     = __float2half_rn(c1);
                g_Vth[(base + d)     * SEQ + s2 + 8] = __float2half_rn(c2);
                g_Vth[(base + d + 1) * SEQ + s2 + 8] = __float2half_rn(c3);
            }
        }
    }
}

// ---------------------------------------------------------------------------
// Output projection: fp16 operands, fp32 result to d_out.
// ---------------------------------------------------------------------------
__global__ __launch_bounds__(256, 2)
void gemm_out(const float* __restrict__ bias, float* __restrict__ C)
{
    extern __shared__ __half smem[];
    const uint32_t smemU = smem_u32(smem);
    const int tid  = threadIdx.x;
    const int wid  = tid >> 5, lane = tid & 31;
    const int wm   = wid & 1, wn = wid >> 1;
    const int qid  = lane >> 2, tig = lane & 3;

    const __half* gA = g_ctxh + (size_t)(blockIdx.y * 128) * EMBED;
    const __half* gB = g_Wh + 3 * (size_t)WELEMS + (size_t)(blockIdx.x * 128) * EMBED;

    float acc[4][4][4] = {};
    GEMM_MAINLOOP(smemU, gA, gB, acc)

    #pragma unroll
    for (int mt = 0; mt < 4; ++mt) {
        const int m = blockIdx.y * 128 + wm * 64 + mt * 16 + qid;
        #pragma unroll
        for (int nt = 0; nt < 4; ++nt) {
            const int n = blockIdx.x * 128 + wn * 32 + nt * 8 + tig * 2;
            const float b0 = bias[n], b1 = bias[n + 1];
            *(float2*)&C[(size_t)m * EMBED + n] =
                make_float2(acc[mt][nt][0] + b0, acc[mt][nt][1] + b1);
            *(float2*)&C[(size_t)(m + 8) * EMBED + n] =
                make_float2(acc[mt][nt][2] + b0, acc[mt][nt][3] + b1);
        }
    }
}

// ---------------------------------------------------------------------------
// Fused flash attention, fp16 (m16n8k16), ldmatrix fragments, ST_F=72.
// ldmatrix banks: row stride 144B -> start bank 4r mod 32, distinct -> clean.
// S C-frag packs directly into the PV A-frag (pack_h2 of c-pairs).
// ---------------------------------------------------------------------------
__global__ __launch_bounds__(256, 2)
void k_flash(const __half* __restrict__ Qg, const __half* __restrict__ Kg,
             const __half* __restrict__ Vtg, __half* __restrict__ ctx)
{
    extern __shared__ __half sm[];
    const uint32_t smemU = smem_u32(sm);
    const uint32_t KsB = BQ * ST_F * 2;              // Ks byte base
    const uint32_t VsB = KsB + 2 * BKV * ST_F * 2;   // Vs byte base

    const int tid = threadIdx.x;
    const int wid = tid >> 5, lane = tid & 31;
    const int qid = lane >> 2, tig = lane & 3;
    const int bh = blockIdx.z;
    const int b = bh >> 4, h = bh & 15;

    const __half* gQ = Qg + ((size_t)bh * SEQ + blockIdx.x * BQ) * HDIM;
    const __half* gK = Kg + (size_t)bh * SEQ * HDIM;
    const __half* gV = Vtg + (size_t)bh * HDIM * SEQ;

    // ldmatrix per-lane byte offsets
    const uint32_t qOff  = ((wid * 16 + (lane & 15)) * ST_F + (lane >> 4) * 8) * 2;
    const uint32_t kvOff = (((lane & 7) + ((lane >> 4) << 3)) * ST_F
                            + ((lane >> 3) & 1) * 8) * 2;

    // Q tile: 128 rows x 64 fp16
    #pragma unroll
    for (int it = 0; it < 4; ++it) {
        int lin = tid + it * 256;
        int r = lin >> 3, c = (lin & 7) * 8;
        cp_async16(smemU + (r * ST_F + c) * 2, gQ + (size_t)r * HDIM + c);
    }
    asm volatile("cp.async.commit_group;" ::: "memory");

    auto loadKV = [&](int j, int buf) {
        uint32_t kd = smemU + KsB + buf * BKV * ST_F * 2;
        uint32_t vd = smemU + VsB + buf * HDIM * ST_F * 2;
        #pragma unroll
        for (int it = 0; it < 2; ++it) {
            int lin = tid + it * 256;
            int r = lin >> 3, c = (lin & 7) * 8;
            cp_async16(kd + (r * ST_F + c) * 2, gK + (size_t)(j * BKV + r) * HDIM + c);
            cp_async16(vd + (r * ST_F + c) * 2, gV + (size_t)r * SEQ + j * BKV + c);
        }
        asm volatile("cp.async.commit_group;" ::: "memory");
    };

    loadKV(0, 0);

    float mrow0 = -1e30f, mrow1 = -1e30f;
    float lrow0 = 0.0f, lrow1 = 0.0f;
    float o[8][4] = {};

    for (int j = 0; j < NJ; ++j) {
        if (j + 1 < NJ) {
            loadKV(j + 1, (j + 1) & 1);
            asm volatile("cp.async.wait_group 1;" ::: "memory");
        } else {
            asm volatile("cp.async.wait_group 0;" ::: "memory");
        }
        __syncthreads();

        // ---- S = Q K^T ----
        float s[8][4] = {};
        const uint32_t kBase = smemU + KsB + (j & 1) * BKV * ST_F * 2 + kvOff;
        const uint32_t qBase = smemU + qOff;
        #pragma unroll
        for (int ks = 0; ks < 4; ++ks) {
            uint32_t af[4];
            ldsm_x4(af, qBase + ks * 32);
            #pragma unroll
            for (int np = 0; np < 4; ++np) {
                uint32_t bq[4];
                ldsm_x4(bq, kBase + np * (16 * ST_F * 2) + ks * 32);
                mma_f16(s[2 * np],     af, bq);
                mma_f16(s[2 * np + 1], af, bq + 2);
            }
        }

        // ---- online softmax (rows rq, rq+8) ----
        float mx0 = -1e30f, mx1 = -1e30f;
        #pragma unroll
        for (int nt = 0; nt < 8; ++nt) {
            s[nt][0] *= SCALE_ATTN; s[nt][1] *= SCALE_ATTN;
            s[nt][2] *= SCALE_ATTN; s[nt][3] *= SCALE_ATTN;
            mx0 = fmaxf(mx0, fmaxf(s[nt][0], s[nt][1]));
            mx1 = fmaxf(mx1, fmaxf(s[nt][2], s[nt][3]));
        }
        mx0 = fmaxf(mx0, __shfl_xor_sync(0xffffffffu, mx0, 1));
        mx0 = fmaxf(mx0, __shfl_xor_sync(0xffffffffu, mx0, 2));
        mx1 = fmaxf(mx1, __shfl_xor_sync(0xffffffffu, mx1, 1));
        mx1 = fmaxf(mx1, __shfl_xor_sync(0xffffffffu, mx1, 2));
        const float mn0 = fmaxf(mrow0, mx0), mn1 = fmaxf(mrow1, mx1);
        const float a0 = __expf(mrow0 - mn0), a1 = __expf(mrow1 - mn1);
        mrow0 = mn0; mrow1 = mn1;

        float sum0 = 0.0f, sum1 = 0.0f;
        #pragma unroll
        for (int nt = 0; nt < 8; ++nt) {
            s[nt][0] = __expf(s[nt][0] - mn0); s[nt][1] = __expf(s[nt][1] - mn0);
            s[nt][2] = __expf(s[nt][2] - mn1); s[nt][3] = __expf(s[nt][3] - mn1);
            sum0 += s[nt][0] + s[nt][1]; sum1 += s[nt][2] + s[nt][3];
        }
        sum0 += __shfl_xor_sync(0xffffffffu, sum0, 1);
        sum0 += __shfl_xor_sync(0xffffffffu, sum0, 2);
        sum1 += __shfl_xor_sync(0xffffffffu, sum1, 1);
        sum1 += __shfl_xor_sync(0xffffffffu, sum1, 2);
        lrow0 = lrow0 * a0 + sum0;
        lrow1 = lrow1 * a1 + sum1;
        #pragma unroll
        for (int nt = 0; nt < 8; ++nt) {
            o[nt][0] *= a0; o[nt][1] *= a0;
            o[nt][2] *= a1; o[nt][3] *= a1;
        }

        // ---- O += P V : A-frag = packed C-frags; B via ldmatrix ----
        const uint32_t vBase = smemU + VsB + (j & 1) * HDIM * ST_F * 2 + kvOff;
        #pragma unroll
        for (int kc = 0; kc < 4; ++kc) {
            uint32_t af[4];
            af[0] = pack_h2(s[2 * kc][0],     s[2 * kc][1]);
            af[1] = pack_h2(s[2 * kc][2],     s[2 * kc][3]);
            af[2] = pack_h2(s[2 * kc + 1][0], s[2 * kc + 1][1]);
            af[3] = pack_h2(s[2 * kc + 1][2], s[2 * kc + 1][3]);
            #pragma unroll
            for (int np = 0; np < 4; ++np) {
                uint32_t bq[4];
                ldsm_x4(bq, vBase + np * (16 * ST_F * 2) + kc * 32);
                mma_f16(o[2 * np],     af, bq);
                mma_f16(o[2 * np + 1], af, bq + 2);
            }
        }
        __syncthreads();
    }

    // ---- epilogue: O /= l, fp16 RN, write ctx [B,S,E] ----
    const float inv0 = 1.0f / lrow0, inv1 = 1.0f / lrow1;
    const int rq = wid * 16 + qid;
    const int q0 = blockIdx.x * BQ + rq;
    __half* dst0 = ctx + ((size_t)b * SEQ + q0) * EMBED + h * HDIM;
    __half* dst1 = ctx + ((size_t)b * SEQ + q0 + 8) * EMBED + h * HDIM;
    #pragma unroll
    for (int nt = 0; nt < 8; ++nt) {
        const int d = nt * 8 + tig * 2;
        *(uint32_t*)&dst0[d] = pack_h2(o[nt][0] * inv0, o[nt][1] * inv0);
        *(uint32_t*)&dst1[d] = pack_h2(o[nt][2] * inv1, o[nt][3] * inv1);
    }
}

// ---------------------------------------------------------------------------
// Launch
// ---------------------------------------------------------------------------
#define SMEM_GEMM  (3 * 256 * ST_H * 2)                    // 61440 B
#define SMEM_FLASH ((BQ + 2 * BKV + 2 * HDIM) * ST_F * 2)  // 55296 B

extern "C" void kernel_launch(void* const* d_in, const int* in_sizes, int n_in,
                              void* d_out, int out_size)
{
    (void)in_sizes; (void)n_in; (void)out_size;
    const float* query = (const float*)d_in[0];
    const float* key   = (const float*)d_in[1];
    const float* value = (const float*)d_in[2];
    const float* Wq = (const float*)d_in[3];  const float* bq = (const float*)d_in[4];
    const float* Wk = (const float*)d_in[5];  const float* bk = (const float*)d_in[6];
    const float* Wv = (const float*)d_in[7];  const float* bv = (const float*)d_in[8];
    const float* Wo = (const float*)d_in[9];  const float* bo = (const float*)d_in[10];
    float* out = (float*)d_out;

    __half *QKh, *Vth, *Cxh;
    cudaGetSymbolAddress((void**)&QKh, g_QKh);
    cudaGetSymbolAddress((void**)&Vth, g_Vth);
    cudaGetSymbolAddress((void**)&Cxh, g_ctxh);

    cudaFuncSetAttribute(gemm_proj, cudaFuncAttributeMaxDynamicSharedMemorySize, SMEM_GEMM);
    cudaFuncSetAttribute(gemm_out,  cudaFuncAttributeMaxDynamicSharedMemorySize, SMEM_GEMM);
    cudaFuncSetAttribute(k_flash,   cudaFuncAttributeMaxDynamicSharedMemorySize, SMEM_FLASH);

    // 1) weight quant-dequant -> fp16; inputs -> fp16
    k_reset<<<1, 32>>>();
    k_absmax<<<dim3(256, 4), 256>>>(Wq, Wk, Wv, Wo);
    k_dequant<<<dim3(WELEMS / (256 * 4), 4), 256>>>(Wq, Wk, Wv, Wo);
    k_cvt_h<<<dim3(TOKENS * EMBED / (256 * 4), 3), 256>>>(query, key, value);

    // 2) fused Q/K/V projections (V written transposed)
    gemm_proj<<<dim3(EMBED / 128, TOKENS / 128, 3), 256, SMEM_GEMM>>>(bq, bk, bv);

    // 3) fused attention -> ctx fp16 [B,S,E]
    const size_t qkOff = (size_t)NBATCH * NHEADS * SEQ * HDIM;
    k_flash<<<dim3(SEQ / BQ, 1, NBATCH * NHEADS), 256, SMEM_FLASH>>>(
        QKh, QKh + qkOff, Vth, Cxh);

    // 4) output projection -> d_out (fp32)
    gemm_out<<<dim3(EMBED / 128, TOKENS / 128, 1), 256, SMEM_GEMM>>>(bo, out);
}

// round 15
// speedup vs baseline: 1.7429x; 1.0242x over previous
#include <cuda_runtime.h>
#include <cuda_fp16.h>
#include <cstdint>

// ---------------------------------------------------------------------------
// Problem constants
// ---------------------------------------------------------------------------
#define EMBED   1024
#define NHEADS  16
#define HDIM    64
#define NBATCH  2
#define SEQ     2048
#define TOKENS  (NBATCH * SEQ)          // 4096
#define WELEMS  (EMBED * EMBED)         // 1048576
#define SCALE_ATTN 0.125f               // 1/sqrt(64), folded into Wq/bq
#define ST_H 40                         // GEMM smem row stride (fp16): 32 data + 8 pad
#define ST_F 72                         // FLASH smem row stride (fp16): 64 data + 8 pad

// Flash-attention tiling
#define BQ   128
#define BKV  64
#define NJ   (SEQ / BKV)                // 32

// ---------------------------------------------------------------------------
// Scratch (static __device__ globals; no runtime allocation allowed)
// ---------------------------------------------------------------------------
__device__ __half g_Wh[4 * WELEMS];                                   // fp16 dequant weights (Wq pre-scaled by 1/8)
__device__ int    g_absmax[4];
__device__ __half g_Xh[3 * (size_t)TOKENS * EMBED];                   // fp16 inputs
__device__ __half g_QKh[2 * (size_t)NBATCH * NHEADS * SEQ * HDIM];    // Q(scaled) then K, [B,H,S,D]
__device__ __half g_Vth[(size_t)NBATCH * NHEADS * HDIM * SEQ];        // [B,H,D,S]
__device__ __half g_ctxh[(size_t)TOKENS * EMBED];                     // [B,S,E]

// ---------------------------------------------------------------------------
// Helpers (target-portable: mma.sync sm_80+, cp.async sm_80+, ldmatrix sm_75+)
// ---------------------------------------------------------------------------
__device__ __forceinline__ uint32_t smem_u32(const void* p) {
    uint32_t a;
    asm("{ .reg .u64 t; cvta.to.shared.u64 t, %1; cvt.u32.u64 %0, t; }" : "=r"(a) : "l"(p));
    return a;
}

__device__ __forceinline__ void cp_async16(uint32_t saddr, const void* gaddr) {
    asm volatile("cp.async.cg.shared.global [%0], [%1], 16;"
                 :: "r"(saddr), "l"(gaddr) : "memory");
}

// D(fp32x4) += A(fp16 4reg) * B(fp16 2reg)  — m16n8k16
__device__ __forceinline__ void mma_f16(float* d, const uint32_t* a, const uint32_t* b) {
    asm volatile(
        "mma.sync.aligned.m16n8k16.row.col.f32.f16.f16.f32 "
        "{%0,%1,%2,%3}, {%4,%5,%6,%7}, {%8,%9}, {%0,%1,%2,%3};"
        : "+f"(d[0]), "+f"(d[1]), "+f"(d[2]), "+f"(d[3])
        : "r"(a[0]), "r"(a[1]), "r"(a[2]), "r"(a[3]), "r"(b[0]), "r"(b[1]));
}

__device__ __forceinline__ void ldsm_x4(uint32_t* r, uint32_t addr) {
    asm volatile("ldmatrix.sync.aligned.m8n8.x4.shared.b16 {%0,%1,%2,%3}, [%4];"
                 : "=r"(r[0]), "=r"(r[1]), "=r"(r[2]), "=r"(r[3]) : "r"(addr));
}

// pack two fp32 -> fp16x2 (lo = first arg), round-to-nearest
__device__ __forceinline__ uint32_t pack_h2(float lo, float hi) {
    uint32_t r;
    asm("cvt.rn.f16x2.f32 %0, %1, %2;" : "=r"(r) : "f"(hi), "f"(lo));
    return r;
}

// ---------------------------------------------------------------------------
// Weight quantization (bit-faithful) -> fp16; Wq additionally scaled by 1/8
// (exponent-only shift: fp16(w/8) == fp16(w)/8 exactly; folds attention scale)
// ---------------------------------------------------------------------------
__global__ void k_reset() { if (threadIdx.x < 4) g_absmax[threadIdx.x] = 0; }

__global__ void k_absmax(const float* __restrict__ w0, const float* __restrict__ w1,
                         const float* __restrict__ w2, const float* __restrict__ w3)
{
    const float* W = (blockIdx.y == 0) ? w0 : (blockIdx.y == 1) ? w1
                   : (blockIdx.y == 2) ? w2 : w3;
    float m = 0.0f;
    for (int i = blockIdx.x * blockDim.x + threadIdx.x; i < WELEMS;
         i += gridDim.x * blockDim.x)
        m = fmaxf(m, fabsf(W[i]));
    #pragma unroll
    for (int o = 16; o; o >>= 1) m = fmaxf(m, __shfl_xor_sync(0xffffffffu, m, o));
    if ((threadIdx.x & 31) == 0) atomicMax(&g_absmax[blockIdx.y], __float_as_int(m));
}

__global__ void k_dequant(const float* __restrict__ w0, const float* __restrict__ w1,
                          const float* __restrict__ w2, const float* __restrict__ w3)
{
    int sel = blockIdx.y;
    const float* W = (sel == 0) ? w0 : (sel == 1) ? w1 : (sel == 2) ? w2 : w3;
    float s = __int_as_float(g_absmax[sel]) / 127.0f;
    const float post = (sel == 0) ? SCALE_ATTN : 1.0f;   // fold attn scale into Wq
    int i = (blockIdx.x * blockDim.x + threadIdx.x) * 4;
    float4 w = *(const float4*)&W[i];
    __half2 h0 = __floats2half2_rn(
        fminf(fmaxf(rintf(w.x / s), -128.0f), 127.0f) * s * post,
        fminf(fmaxf(rintf(w.y / s), -128.0f), 127.0f) * s * post);
    __half2 h1 = __floats2half2_rn(
        fminf(fmaxf(rintf(w.z / s), -128.0f), 127.0f) * s * post,
        fminf(fmaxf(rintf(w.w / s), -128.0f), 127.0f) * s * post);
    *(__half2*)&g_Wh[(size_t)sel * WELEMS + i]     = h0;
    *(__half2*)&g_Wh[(size_t)sel * WELEMS + i + 2] = h1;
}

__global__ void k_cvt_h(const float* __restrict__ q, const float* __restrict__ k,
                        const float* __restrict__ v)
{
    int sel = blockIdx.y;
    const float* s = (sel == 0) ? q : (sel == 1) ? k : v;
    __half* d = g_Xh + (size_t)sel * TOKENS * EMBED;
    int i = (blockIdx.x * blockDim.x + threadIdx.x) * 4;
    float4 w = *(const float4*)&s[i];
    *(__half2*)&d[i]     = __floats2half2_rn(w.x, w.y);
    *(__half2*)&d[i + 2] = __floats2half2_rn(w.z, w.w);
}

// ---------------------------------------------------------------------------
// fp16 NT GEMM mainloop (m16n8k16), NS=3 cp.async, ldmatrix fragments.
// ---------------------------------------------------------------------------
#define GEMM_MAINLOOP(SMEMU, GA, GB, ACC)                                        \
    const uint32_t aOff = ((wm * 64 + (lane & 15)) * ST_H + (lane >> 4) * 8) * 2;\
    const uint32_t bOff = ((wn * 32 + (lane & 7) + ((lane >> 4) << 3)) * ST_H    \
                           + ((lane >> 3) & 1) * 8) * 2;                         \
    auto loadStage = [&](int st, int k0) {                                       \
        uint32_t sAp = (SMEMU) + st * (256 * ST_H * 2);                          \
        uint32_t sBp = sAp + 128 * ST_H * 2;                                     \
        const int r0 = tid >> 2, c = (tid & 3) * 8;                              \
        _Pragma("unroll")                                                        \
        for (int it = 0; it < 2; ++it) {                                         \
            const int r = r0 + it * 64;                                          \
            cp_async16(sAp + (r * ST_H + c) * 2, (GA) + (size_t)r * EMBED + k0 + c); \
        }                                                                        \
        _Pragma("unroll")                                                        \
        for (int it = 0; it < 2; ++it) {                                         \
            const int r = r0 + it * 64;                                          \
            cp_async16(sBp + (r * ST_H + c) * 2, (GB) + (size_t)r * EMBED + k0 + c); \
        }                                                                        \
        asm volatile("cp.async.commit_group;" ::: "memory");                     \
    };                                                                           \
    const int ns = EMBED / 32;                                                   \
    loadStage(0, 0);                                                             \
    loadStage(1, 32);                                                            \
    for (int i = 0; i < ns; ++i) {                                               \
        if (i + 1 < ns) { asm volatile("cp.async.wait_group 1;" ::: "memory"); } \
        else            { asm volatile("cp.async.wait_group 0;" ::: "memory"); } \
        __syncthreads();                                                         \
        if (i + 2 < ns) loadStage((i + 2) % 3, (i + 2) * 32);                    \
        const uint32_t aBase = (SMEMU) + (i % 3) * (256 * ST_H * 2) + aOff;      \
        const uint32_t bBase = (SMEMU) + (i % 3) * (256 * ST_H * 2)              \
                               + 128 * ST_H * 2 + bOff;                          \
        _Pragma("unroll")                                                        \
        for (int ks = 0; ks < 2; ++ks) {                                         \
            uint32_t af[4][4], bq[2][4];                                         \
            _Pragma("unroll")                                                    \
            for (int mt = 0; mt < 4; ++mt)                                       \
                ldsm_x4(af[mt], aBase + mt * (16 * ST_H * 2) + ks * 32);         \
            _Pragma("unroll")                                                    \
            for (int np = 0; np < 2; ++np)                                       \
                ldsm_x4(bq[np], bBase + np * (16 * ST_H * 2) + ks * 32);         \
            _Pragma("unroll")                                                    \
            for (int mt = 0; mt < 4; ++mt)                                       \
                _Pragma("unroll")                                                \
                for (int nt = 0; nt < 4; ++nt)                                   \
                    mma_f16(ACC[mt][nt], af[mt], &bq[nt >> 1][(nt & 1) * 2]);    \
        }                                                                        \
    }

// ---------------------------------------------------------------------------
// Fused Q/K/V projection (grid z in {0,1,2}); fp16 in, fp16 out.
// z==0 bias scaled by 1/8 to match the pre-scaled Wq.
// ---------------------------------------------------------------------------
__global__ __launch_bounds__(256, 2)
void gemm_proj(const float* __restrict__ b0, const float* __restrict__ b1,
               const float* __restrict__ b2)
{
    extern __shared__ __half smem[];
    const uint32_t smemU = smem_u32(smem);
    const int tid  = threadIdx.x;
    const int wid  = tid >> 5, lane = tid & 31;
    const int wm   = wid & 1, wn = wid >> 1;
    const int qid  = lane >> 2, tig = lane & 3;
    const int z    = blockIdx.z;

    const float* bias = (z == 0) ? b0 : (z == 1) ? b1 : b2;
    const float bscale = (z == 0) ? SCALE_ATTN : 1.0f;
    const __half* gA = g_Xh + (size_t)z * TOKENS * EMBED + (size_t)(blockIdx.y * 128) * EMBED;
    const __half* gB = g_Wh + (size_t)z * WELEMS + (size_t)(blockIdx.x * 128) * EMBED;

    float acc[4][4][4] = {};
    GEMM_MAINLOOP(smemU, gA, gB, acc)

    #pragma unroll
    for (int mt = 0; mt < 4; ++mt) {
        const int m = blockIdx.y * 128 + wm * 64 + mt * 16 + qid;
        const int b = m >> 11, s2 = m & (SEQ - 1);
        #pragma unroll
        for (int nt = 0; nt < 4; ++nt) {
            const int n = blockIdx.x * 128 + wn * 32 + nt * 8 + tig * 2;
            const int h = n >> 6, d = n & (HDIM - 1);
            const float bb0 = bias[n] * bscale, bb1 = bias[n + 1] * bscale;
            const float c0 = acc[mt][nt][0] + bb0, c1 = acc[mt][nt][1] + bb1;
            const float c2 = acc[mt][nt][2] + bb0, c3 = acc[mt][nt][3] + bb1;
            if (z < 2) {
                __half* C = g_QKh + (size_t)z * ((size_t)NBATCH * NHEADS * SEQ * HDIM);
                const size_t base = ((size_t)b * NHEADS + h) * SEQ;
                *(uint32_t*)&C[(base + s2) * HDIM + d]     = pack_h2(c0, c1);
                *(uint32_t*)&C[(base + s2 + 8) * HDIM + d] = pack_h2(c2, c3);
            } else {
                const size_t base = ((size_t)b * NHEADS + h) * HDIM;
                g_Vth[(base + d)     * SEQ + s2]     = __float2half_rn(c0);
                g_Vth[(base + d + 1) * SEQ + s2]     = __float2half_rn(c1);
                g_Vth[(base + d)     * SEQ + s2 + 8] = __float2half_rn(c2);
                g_Vth[(base + d + 1) * SEQ + s2 + 8] = __float2half_rn(c3);
            }
        }
    }
}

// ---------------------------------------------------------------------------
// Output projection: fp16 operands, fp32 result to d_out.
// ---------------------------------------------------------------------------
__global__ __launch_bounds__(256, 2)
void gemm_out(const float* __restrict__ bias, float* __restrict__ C)
{
    extern __shared__ __half smem[];
    const uint32_t smemU = smem_u32(smem);
    const int tid  = threadIdx.x;
    const int wid  = tid >> 5, lane = tid & 31;
    const int wm   = wid & 1, wn = wid >> 1;
    const int qid  = lane >> 2, tig = lane & 3;

    const __half* gA = g_ctxh + (size_t)(blockIdx.y * 128) * EMBED;
    const __half* gB = g_Wh + 3 * (size_t)WELEMS + (size_t)(blockIdx.x * 128) * EMBED;

    float acc[4][4][4] = {};
    GEMM_MAINLOOP(smemU, gA, gB, acc)

    #pragma unroll
    for (int mt = 0; mt < 4; ++mt) {
        const int m = blockIdx.y * 128 + wm * 64 + mt * 16 + qid;
        #pragma unroll
        for (int nt = 0; nt < 4; ++nt) {
            const int n = blockIdx.x * 128 + wn * 32 + nt * 8 + tig * 2;
            const float b0 = bias[n], b1 = bias[n + 1];
            *(float2*)&C[(size_t)m * EMBED + n] =
                make_float2(acc[mt][nt][0] + b0, acc[mt][nt][1] + b1);
            *(float2*)&C[(size_t)(m + 8) * EMBED + n] =
                make_float2(acc[mt][nt][2] + b0, acc[mt][nt][3] + b1);
        }
    }
}

// ---------------------------------------------------------------------------
// Fused flash attention, fp16 (m16n8k16), ldmatrix fragments, ST_F=72.
// v2: single __syncthreads per KV iter (prefetch issued AFTER the sync, so
//     the WAR on the ping-pong buffer is covered by the same barrier);
//     Q fragments hoisted to registers at j==0 (loop-invariant);
//     attention scale pre-folded into Q (no FMULs here).
// ---------------------------------------------------------------------------
__global__ __launch_bounds__(256, 2)
void k_flash(const __half* __restrict__ Qg, const __half* __restrict__ Kg,
             const __half* __restrict__ Vtg, __half* __restrict__ ctx)
{
    extern __shared__ __half sm[];
    const uint32_t smemU = smem_u32(sm);
    const uint32_t KsB = BQ * ST_F * 2;              // Ks byte base
    const uint32_t VsB = KsB + 2 * BKV * ST_F * 2;   // Vs byte base

    const int tid = threadIdx.x;
    const int wid = tid >> 5, lane = tid & 31;
    const int qid = lane >> 2, tig = lane & 3;
    const int bh = blockIdx.z;
    const int b = bh >> 4, h = bh & 15;

    const __half* gQ = Qg + ((size_t)bh * SEQ + blockIdx.x * BQ) * HDIM;
    const __half* gK = Kg + (size_t)bh * SEQ * HDIM;
    const __half* gV = Vtg + (size_t)bh * HDIM * SEQ;

    // ldmatrix per-lane byte offsets
    const uint32_t qOff  = ((wid * 16 + (lane & 15)) * ST_F + (lane >> 4) * 8) * 2;
    const uint32_t kvOff = (((lane & 7) + ((lane >> 4) << 3)) * ST_F
                            + ((lane >> 3) & 1) * 8) * 2;

    // Q tile: 128 rows x 64 fp16 (one group)
    #pragma unroll
    for (int it = 0; it < 4; ++it) {
        int lin = tid + it * 256;
        int r = lin >> 3, c = (lin & 7) * 8;
        cp_async16(smemU + (r * ST_F + c) * 2, gQ + (size_t)r * HDIM + c);
    }
    asm volatile("cp.async.commit_group;" ::: "memory");

    auto loadKV = [&](int j, int buf) {
        uint32_t kd = smemU + KsB + buf * BKV * ST_F * 2;
        uint32_t vd = smemU + VsB + buf * HDIM * ST_F * 2;
        #pragma unroll
        for (int it = 0; it < 2; ++it) {
            int lin = tid + it * 256;
            int r = lin >> 3, c = (lin & 7) * 8;
            cp_async16(kd + (r * ST_F + c) * 2, gK + (size_t)(j * BKV + r) * HDIM + c);
            cp_async16(vd + (r * ST_F + c) * 2, gV + (size_t)r * SEQ + j * BKV + c);
        }
        asm volatile("cp.async.commit_group;" ::: "memory");
    };

    loadKV(0, 0);

    float mrow0 = -1e30f, mrow1 = -1e30f;
    float lrow0 = 0.0f, lrow1 = 0.0f;
    float o[8][4] = {};
    uint32_t qf[4][4];                               // loop-invariant Q fragments

    for (int j = 0; j < NJ; ++j) {
        // exactly one cp.async group pending here (KV j; plus Q at j==0)
        asm volatile("cp.async.wait_group 0;" ::: "memory");
        __syncthreads();    // publishes KV j AND certifies all warps done with
                            // iter j-1's buffer (= the one prefetched below)
        if (j + 1 < NJ) loadKV(j + 1, (j + 1) & 1);
        if (j == 0) {
            #pragma unroll
            for (int ks = 0; ks < 4; ++ks)
                ldsm_x4(qf[ks], smemU + qOff + ks * 32);
        }

        // ---- S = Q K^T (scale pre-folded into Q) ----
        float s[8][4] = {};
        const uint32_t kBase = smemU + KsB + (j & 1) * BKV * ST_F * 2 + kvOff;
        #pragma unroll
        for (int ks = 0; ks < 4; ++ks) {
            #pragma unroll
            for (int np = 0; np < 4; ++np) {
                uint32_t bq[4];
                ldsm_x4(bq, kBase + np * (16 * ST_F * 2) + ks * 32);
                mma_f16(s[2 * np],     qf[ks], bq);
                mma_f16(s[2 * np + 1], qf[ks], bq + 2);
            }
        }

        // ---- online softmax (rows rq, rq+8) ----
        float mx0 = -1e30f, mx1 = -1e30f;
        #pragma unroll
        for (int nt = 0; nt < 8; ++nt) {
            mx0 = fmaxf(mx0, fmaxf(s[nt][0], s[nt][1]));
            mx1 = fmaxf(mx1, fmaxf(s[nt][2], s[nt][3]));
        }
        mx0 = fmaxf(mx0, __shfl_xor_sync(0xffffffffu, mx0, 1));
        mx0 = fmaxf(mx0, __shfl_xor_sync(0xffffffffu, mx0, 2));
        mx1 = fmaxf(mx1, __shfl_xor_sync(0xffffffffu, mx1, 1));
        mx1 = fmaxf(mx1, __shfl_xor_sync(0xffffffffu, mx1, 2));
        const float mn0 = fmaxf(mrow0, mx0), mn1 = fmaxf(mrow1, mx1);
        const float a0 = __expf(mrow0 - mn0), a1 = __expf(mrow1 - mn1);
        mrow0 = mn0; mrow1 = mn1;

        float sum0 = 0.0f, sum1 = 0.0f;
        #pragma unroll
        for (int nt = 0; nt < 8; ++nt) {
            s[nt][0] = __expf(s[nt][0] - mn0); s[nt][1] = __expf(s[nt][1] - mn0);
            s[nt][2] = __expf(s[nt][2] - mn1); s[nt][3] = __expf(s[nt][3] - mn1);
            sum0 += s[nt][0] + s[nt][1]; sum1 += s[nt][2] + s[nt][3];
        }
        sum0 += __shfl_xor_sync(0xffffffffu, sum0, 1);
        sum0 += __shfl_xor_sync(0xffffffffu, sum0, 2);
        sum1 += __shfl_xor_sync(0xffffffffu, sum1, 1);
        sum1 += __shfl_xor_sync(0xffffffffu, sum1, 2);
        lrow0 = lrow0 * a0 + sum0;
        lrow1 = lrow1 * a1 + sum1;
        #pragma unroll
        for (int nt = 0; nt < 8; ++nt) {
            o[nt][0] *= a0; o[nt][1] *= a0;
            o[nt][2] *= a1; o[nt][3] *= a1;
        }

        // ---- O += P V : A-frag = packed C-frags; B via ldmatrix ----
        const uint32_t vBase = smemU + VsB + (j & 1) * HDIM * ST_F * 2 + kvOff;
        #pragma unroll
        for (int kc = 0; kc < 4; ++kc) {
            uint32_t af[4];
            af[0] = pack_h2(s[2 * kc][0],     s[2 * kc][1]);
            af[1] = pack_h2(s[2 * kc][2],     s[2 * kc][3]);
            af[2] = pack_h2(s[2 * kc + 1][0], s[2 * kc + 1][1]);
            af[3] = pack_h2(s[2 * kc + 1][2], s[2 * kc + 1][3]);
            #pragma unroll
            for (int np = 0; np < 4; ++np) {
                uint32_t bq[4];
                ldsm_x4(bq, vBase + np * (16 * ST_F * 2) + kc * 32);
                mma_f16(o[2 * np],     af, bq);
                mma_f16(o[2 * np + 1], af, bq + 2);
            }
        }
        // no bottom barrier: next iteration's top sync covers the WAR
    }

    // ---- epilogue: O /= l, fp16 RN, write ctx [B,S,E] ----
    const float inv0 = 1.0f / lrow0, inv1 = 1.0f / lrow1;
    const int rq = wid * 16 + qid;
    const int q0 = blockIdx.x * BQ + rq;
    __half* dst0 = ctx + ((size_t)b * SEQ + q0) * EMBED + h * HDIM;
    __half* dst1 = ctx + ((size_t)b * SEQ + q0 + 8) * EMBED + h * HDIM;
    #pragma unroll
    for (int nt = 0; nt < 8; ++nt) {
        const int d = nt * 8 + tig * 2;
        *(uint32_t*)&dst0[d] = pack_h2(o[nt][0] * inv0, o[nt][1] * inv0);
        *(uint32_t*)&dst1[d] = pack_h2(o[nt][2] * inv1, o[nt][3] * inv1);
    }
}

// ---------------------------------------------------------------------------
// Launch
// ---------------------------------------------------------------------------
#define SMEM_GEMM  (3 * 256 * ST_H * 2)                    // 61440 B
#define SMEM_FLASH ((BQ + 2 * BKV + 2 * HDIM) * ST_F * 2)  // 55296 B

extern "C" void kernel_launch(void* const* d_in, const int* in_sizes, int n_in,
                              void* d_out, int out_size)
{
    (void)in_sizes; (void)n_in; (void)out_size;
    const float* query = (const float*)d_in[0];
    const float* key   = (const float*)d_in[1];
    const float* value = (const float*)d_in[2];
    const float* Wq = (const float*)d_in[3];  const float* bq = (const float*)d_in[4];
    const float* Wk = (const float*)d_in[5];  const float* bk = (const float*)d_in[6];
    const float* Wv = (const float*)d_in[7];  const float* bv = (const float*)d_in[8];
    const float* Wo = (const float*)d_in[9];  const float* bo = (const float*)d_in[10];
    float* out = (float*)d_out;

    __half *QKh, *Vth, *Cxh;
    cudaGetSymbolAddress((void**)&QKh, g_QKh);
    cudaGetSymbolAddress((void**)&Vth, g_Vth);
    cudaGetSymbolAddress((void**)&Cxh, g_ctxh);

    cudaFuncSetAttribute(gemm_proj, cudaFuncAttributeMaxDynamicSharedMemorySize, SMEM_GEMM);
    cudaFuncSetAttribute(gemm_out,  cudaFuncAttributeMaxDynamicSharedMemorySize, SMEM_GEMM);
    cudaFuncSetAttribute(k_flash,   cudaFuncAttributeMaxDynamicSharedMemorySize, SMEM_FLASH);

    // 1) weight quant-dequant -> fp16 (Wq pre-scaled); inputs -> fp16
    k_reset<<<1, 32>>>();
    k_absmax<<<dim3(256, 4), 256>>>(Wq, Wk, Wv, Wo);
    k_dequant<<<dim3(WELEMS / (256 * 4), 4), 256>>>(Wq, Wk, Wv, Wo);
    k_cvt_h<<<dim3(TOKENS * EMBED / (256 * 4), 3), 256>>>(query, key, value);

    // 2) fused Q/K/V projections (V written transposed; Q pre-scaled)
    gemm_proj<<<dim3(EMBED / 128, TOKENS / 128, 3), 256, SMEM_GEMM>>>(bq, bk, bv);

    // 3) fused attention -> ctx fp16 [B,S,E]
    const size_t qkOff = (size_t)NBATCH * NHEADS * SEQ * HDIM;
    k_flash<<<dim3(SEQ / BQ, 1, NBATCH * NHEADS), 256, SMEM_FLASH>>>(
        QKh, QKh + qkOff, Vth, Cxh);

    // 4) output projection -> d_out (fp32)
    gemm_out<<<dim3(EMBED / 128, TOKENS / 128, 1), 256, SMEM_GEMM>>>(bo, out);
}

// round 16
// speedup vs baseline: 1.7565x; 1.0078x over previous
#include <cuda_runtime.h>
#include <cuda_fp16.h>
#include <cstdint>

// ---------------------------------------------------------------------------
// Problem constants
// ---------------------------------------------------------------------------
#define EMBED   1024
#define NHEADS  16
#define HDIM    64
#define NBATCH  2
#define SEQ     2048
#define TOKENS  (NBATCH * SEQ)          // 4096
#define WELEMS  (EMBED * EMBED)         // 1048576
#define SCALE_Q 0.18033688f             // (1/8) * log2(e): attn scale + exp2 base folded into Wq/bq
#define ST_H 40                         // GEMM smem row stride (fp16): 32 data + 8 pad
#define ST_F 72                         // flash K/Q row stride (fp16): 64 data + 8 pad
#define STV  136                        // flash V row stride (fp16): 128 keys + 8 pad

// Flash tiling: 128 keys per load (two 64-key compute sub-tiles)
#define BQ    128
#define BKV2  128
#define NJ2   (SEQ / BKV2)              // 16

// ---------------------------------------------------------------------------
// Scratch (static __device__ globals; no runtime allocation allowed)
// ---------------------------------------------------------------------------
__device__ __half g_Wh[4 * WELEMS];                                   // fp16 dequant weights (Wq pre-scaled)
__device__ int    g_absmax[4];
__device__ __half g_Xh[3 * (size_t)TOKENS * EMBED];                   // fp16 inputs
__device__ __half g_QKh[2 * (size_t)NBATCH * NHEADS * SEQ * HDIM];    // Q(scaled) then K, [B,H,S,D]
__device__ __half g_Vth[(size_t)NBATCH * NHEADS * HDIM * SEQ];        // [B,H,D,S]
__device__ __half g_ctxh[(size_t)TOKENS * EMBED];                     // [B,S,E]

// ---------------------------------------------------------------------------
// Helpers (target-portable: mma.sync sm_80+, cp.async sm_80+, ldmatrix sm_75+)
// ---------------------------------------------------------------------------
__device__ __forceinline__ uint32_t smem_u32(const void* p) {
    uint32_t a;
    asm("{ .reg .u64 t; cvta.to.shared.u64 t, %1; cvt.u32.u64 %0, t; }" : "=r"(a) : "l"(p));
    return a;
}

__device__ __forceinline__ void cp_async16(uint32_t saddr, const void* gaddr) {
    asm volatile("cp.async.cg.shared.global [%0], [%1], 16;"
                 :: "r"(saddr), "l"(gaddr) : "memory");
}

__device__ __forceinline__ void mma_f16(float* d, const uint32_t* a, const uint32_t* b) {
    asm volatile(
        "mma.sync.aligned.m16n8k16.row.col.f32.f16.f16.f32 "
        "{%0,%1,%2,%3}, {%4,%5,%6,%7}, {%8,%9}, {%0,%1,%2,%3};"
        : "+f"(d[0]), "+f"(d[1]), "+f"(d[2]), "+f"(d[3])
        : "r"(a[0]), "r"(a[1]), "r"(a[2]), "r"(a[3]), "r"(b[0]), "r"(b[1]));
}

__device__ __forceinline__ void ldsm_x4(uint32_t* r, uint32_t addr) {
    asm volatile("ldmatrix.sync.aligned.m8n8.x4.shared.b16 {%0,%1,%2,%3}, [%4];"
                 : "=r"(r[0]), "=r"(r[1]), "=r"(r[2]), "=r"(r[3]) : "r"(addr));
}

__device__ __forceinline__ uint32_t pack_h2(float lo, float hi) {
    uint32_t r;
    asm("cvt.rn.f16x2.f32 %0, %1, %2;" : "=r"(r) : "f"(hi), "f"(lo));
    return r;
}

__device__ __forceinline__ float ex2(float x) {
    float r;
    asm("ex2.approx.f32 %0, %1;" : "=f"(r) : "f"(x));
    return r;
}

// ---------------------------------------------------------------------------
// Weight quantization (bit-faithful) + input conversion, one merged pass.
// Wq (sel 0) pre-scaled by (1/8)*log2e so flash softmax runs in base-2.
// ---------------------------------------------------------------------------
__global__ void k_reset() { if (threadIdx.x < 4) g_absmax[threadIdx.x] = 0; }

__global__ void k_absmax(const float* __restrict__ w0, const float* __restrict__ w1,
                         const float* __restrict__ w2, const float* __restrict__ w3)
{
    const float* W = (blockIdx.y == 0) ? w0 : (blockIdx.y == 1) ? w1
                   : (blockIdx.y == 2) ? w2 : w3;
    float m = 0.0f;
    for (int i = blockIdx.x * blockDim.x + threadIdx.x; i < WELEMS;
         i += gridDim.x * blockDim.x)
        m = fmaxf(m, fabsf(W[i]));
    #pragma unroll
    for (int o = 16; o; o >>= 1) m = fmaxf(m, __shfl_xor_sync(0xffffffffu, m, o));
    if ((threadIdx.x & 31) == 0) atomicMax(&g_absmax[blockIdx.y], __float_as_int(m));
}

// grid (4096, 4): y<3 -> input cvt (sel=y); y==3 -> weight dequant
// (sel = blockIdx.x>>10, 1024 blocks per weight tensor)
__global__ void k_prep(const float* __restrict__ q, const float* __restrict__ k,
                       const float* __restrict__ v,
                       const float* __restrict__ w0, const float* __restrict__ w1,
                       const float* __restrict__ w2, const float* __restrict__ w3)
{
    const int y = blockIdx.y;
    if (y < 3) {
        const float* s = (y == 0) ? q : (y == 1) ? k : v;
        __half* d = g_Xh + (size_t)y * TOKENS * EMBED;
        int i = (blockIdx.x * blockDim.x + threadIdx.x) * 4;
        float4 w = *(const float4*)&s[i];
        *(__half2*)&d[i]     = __floats2half2_rn(w.x, w.y);
        *(__half2*)&d[i + 2] = __floats2half2_rn(w.z, w.w);
    } else {
        const int sel = blockIdx.x >> 10;
        const int bx  = blockIdx.x & 1023;
        const float* W = (sel == 0) ? w0 : (sel == 1) ? w1 : (sel == 2) ? w2 : w3;
        float sc = __int_as_float(g_absmax[sel]) / 127.0f;
        const float post = (sel == 0) ? SCALE_Q : 1.0f;
        int i = (bx * blockDim.x + threadIdx.x) * 4;
        float4 w = *(const float4*)&W[i];
        __half2 h0 = __floats2half2_rn(
            fminf(fmaxf(rintf(w.x / sc), -128.0f), 127.0f) * sc * post,
            fminf(fmaxf(rintf(w.y / sc), -128.0f), 127.0f) * sc * post);
        __half2 h1 = __floats2half2_rn(
            fminf(fmaxf(rintf(w.z / sc), -128.0f), 127.0f) * sc * post,
            fminf(fmaxf(rintf(w.w / sc), -128.0f), 127.0f) * sc * post);
        *(__half2*)&g_Wh[(size_t)sel * WELEMS + i]     = h0;
        *(__half2*)&g_Wh[(size_t)sel * WELEMS + i + 2] = h1;
    }
}

// ---------------------------------------------------------------------------
// fp16 NT GEMM mainloop (m16n8k16), NS=3 cp.async, ldmatrix fragments.
// ---------------------------------------------------------------------------
#define GEMM_MAINLOOP(SMEMU, GA, GB, ACC)                                        \
    const uint32_t aOff = ((wm * 64 + (lane & 15)) * ST_H + (lane >> 4) * 8) * 2;\
    const uint32_t bOff = ((wn * 32 + (lane & 7) + ((lane >> 4) << 3)) * ST_H    \
                           + ((lane >> 3) & 1) * 8) * 2;                         \
    auto loadStage = [&](int st, int k0) {                                       \
        uint32_t sAp = (SMEMU) + st * (256 * ST_H * 2);                          \
        uint32_t sBp = sAp + 128 * ST_H * 2;                                     \
        const int r0 = tid >> 2, c = (tid & 3) * 8;                              \
        _Pragma("unroll")                                                        \
        for (int it = 0; it < 2; ++it) {                                         \
            const int r = r0 + it * 64;                                          \
            cp_async16(sAp + (r * ST_H + c) * 2, (GA) + (size_t)r * EMBED + k0 + c); \
        }                                                                        \
        _Pragma("unroll")                                                        \
        for (int it = 0; it < 2; ++it) {                                         \
            const int r = r0 + it * 64;                                          \
            cp_async16(sBp + (r * ST_H + c) * 2, (GB) + (size_t)r * EMBED + k0 + c); \
        }                                                                        \
        asm volatile("cp.async.commit_group;" ::: "memory");                     \
    };                                                                           \
    const int ns = EMBED / 32;                                                   \
    loadStage(0, 0);                                                             \
    loadStage(1, 32);                                                            \
    for (int i = 0; i < ns; ++i) {                                               \
        if (i + 1 < ns) { asm volatile("cp.async.wait_group 1;" ::: "memory"); } \
        else            { asm volatile("cp.async.wait_group 0;" ::: "memory"); } \
        __syncthreads();                                                         \
        if (i + 2 < ns) loadStage((i + 2) % 3, (i + 2) * 32);                    \
        const uint32_t aBase = (SMEMU) + (i % 3) * (256 * ST_H * 2) + aOff;      \
        const uint32_t bBase = (SMEMU) + (i % 3) * (256 * ST_H * 2)              \
                               + 128 * ST_H * 2 + bOff;                          \
        _Pragma("unroll")                                                        \
        for (int ks = 0; ks < 2; ++ks) {                                         \
            uint32_t af[4][4], bq[2][4];                                         \
            _Pragma("unroll")                                                    \
            for (int mt = 0; mt < 4; ++mt)                                       \
                ldsm_x4(af[mt], aBase + mt * (16 * ST_H * 2) + ks * 32);         \
            _Pragma("unroll")                                                    \
            for (int np = 0; np < 2; ++np)                                       \
                ldsm_x4(bq[np], bBase + np * (16 * ST_H * 2) + ks * 32);         \
            _Pragma("unroll")                                                    \
            for (int mt = 0; mt < 4; ++mt)                                       \
                _Pragma("unroll")                                                \
                for (int nt = 0; nt < 4; ++nt)                                   \
                    mma_f16(ACC[mt][nt], af[mt], &bq[nt >> 1][(nt & 1) * 2]);    \
        }                                                                        \
    }

// ---------------------------------------------------------------------------
// Fused Q/K/V projection (grid z in {0,1,2}); fp16 in, fp16 out.
// z==0 bias scaled by SCALE_Q to match the pre-scaled Wq.
// ---------------------------------------------------------------------------
__global__ __launch_bounds__(256, 2)
void gemm_proj(const float* __restrict__ b0, const float* __restrict__ b1,
               const float* __restrict__ b2)
{
    extern __shared__ __half smem[];
    const uint32_t smemU = smem_u32(smem);
    const int tid  = threadIdx.x;
    const int wid  = tid >> 5, lane = tid & 31;
    const int wm   = wid & 1, wn = wid >> 1;
    const int qid  = lane >> 2, tig = lane & 3;
    const int z    = blockIdx.z;

    const float* bias = (z == 0) ? b0 : (z == 1) ? b1 : b2;
    const float bscale = (z == 0) ? SCALE_Q : 1.0f;
    const __half* gA = g_Xh + (size_t)z * TOKENS * EMBED + (size_t)(blockIdx.y * 128) * EMBED;
    const __half* gB = g_Wh + (size_t)z * WELEMS + (size_t)(blockIdx.x * 128) * EMBED;

    float acc[4][4][4] = {};
    GEMM_MAINLOOP(smemU, gA, gB, acc)

    #pragma unroll
    for (int mt = 0; mt < 4; ++mt) {
        const int m = blockIdx.y * 128 + wm * 64 + mt * 16 + qid;
        const int b = m >> 11, s2 = m & (SEQ - 1);
        #pragma unroll
        for (int nt = 0; nt < 4; ++nt) {
            const int n = blockIdx.x * 128 + wn * 32 + nt * 8 + tig * 2;
            const int h = n >> 6, d = n & (HDIM - 1);
            const float bb0 = bias[n] * bscale, bb1 = bias[n + 1] * bscale;
            const float c0 = acc[mt][nt][0] + bb0, c1 = acc[mt][nt][1] + bb1;
            const float c2 = acc[mt][nt][2] + bb0, c3 = acc[mt][nt][3] + bb1;
            if (z < 2) {
                __half* C = g_QKh + (size_t)z * ((size_t)NBATCH * NHEADS * SEQ * HDIM);
                const size_t base = ((size_t)b * NHEADS + h) * SEQ;
                *(uint32_t*)&C[(base + s2) * HDIM + d]     = pack_h2(c0, c1);
                *(uint32_t*)&C[(base + s2 + 8) * HDIM + d] = pack_h2(c2, c3);
            } else {
                const size_t base = ((size_t)b * NHEADS + h) * HDIM;
                g_Vth[(base + d)     * SEQ + s2]     = __float2half_rn(c0);
                g_Vth[(base + d + 1) * SEQ + s2]     = __float2half_rn(c1);
                g_Vth[(base + d)     * SEQ + s2 + 8] = __float2half_rn(c2);
                g_Vth[(base + d + 1) * SEQ + s2 + 8] = __float2half_rn(c3);
            }
        }
    }
}

// ---------------------------------------------------------------------------
// Output projection: fp16 operands, fp32 result to d_out.
// ---------------------------------------------------------------------------
__global__ __launch_bounds__(256, 2)
void gemm_out(const float* __restrict__ bias, float* __restrict__ C)
{
    extern __shared__ __half smem[];
    const uint32_t smemU = smem_u32(smem);
    const int tid  = threadIdx.x;
    const int wid  = tid >> 5, lane = tid & 31;
    const int wm   = wid & 1, wn = wid >> 1;
    const int qid  = lane >> 2, tig = lane & 3;

    const __half* gA = g_ctxh + (size_t)(blockIdx.y * 128) * EMBED;
    const __half* gB = g_Wh + 3 * (size_t)WELEMS + (size_t)(blockIdx.x * 128) * EMBED;

    float acc[4][4][4] = {};
    GEMM_MAINLOOP(smemU, gA, gB, acc)

    #pragma unroll
    for (int mt = 0; mt < 4; ++mt) {
        const int m = blockIdx.y * 128 + wm * 64 + mt * 16 + qid;
        #pragma unroll
        for (int nt = 0; nt < 4; ++nt) {
            const int n = blockIdx.x * 128 + wn * 32 + nt * 8 + tig * 2;
            const float b0 = bias[n], b1 = bias[n + 1];
            *(float2*)&C[(size_t)m * EMBED + n] =
                make_float2(acc[mt][nt][0] + b0, acc[mt][nt][1] + b1);
            *(float2*)&C[(size_t)(m + 8) * EMBED + n] =
                make_float2(acc[mt][nt][2] + b0, acc[mt][nt][3] + b1);
        }
    }
}

// ---------------------------------------------------------------------------
// Fused flash attention, fp16 (m16n8k16), ldmatrix fragments.
// v3: 128 keys loaded per cp.async group (two 64-key compute sub-tiles per
//     barrier -> 16 barriers instead of 32); base-2 softmax (scale+log2e
//     folded into Q), raw ex2.approx; Q fragments hoisted to registers.
// ---------------------------------------------------------------------------
__global__ __launch_bounds__(256, 2)
void k_flash(const __half* __restrict__ Qg, const __half* __restrict__ Kg,
             const __half* __restrict__ Vtg, __half* __restrict__ ctx)
{
    extern __shared__ __half sm[];
    const uint32_t smemU = smem_u32(sm);
    const uint32_t KsB = BQ * ST_F * 2;               // K ring base (bytes)
    const uint32_t VsB = KsB + 2 * BKV2 * ST_F * 2;   // V ring base

    const int tid = threadIdx.x;
    const int wid = tid >> 5, lane = tid & 31;
    const int qid = lane >> 2, tig = lane & 3;
    const int bh = blockIdx.z;
    const int b = bh >> 4, h = bh & 15;

    const __half* gQ = Qg + ((size_t)bh * SEQ + blockIdx.x * BQ) * HDIM;
    const __half* gK = Kg + (size_t)bh * SEQ * HDIM;
    const __half* gV = Vtg + (size_t)bh * HDIM * SEQ;

    // ldmatrix per-lane byte offsets
    const uint32_t qOff  = ((wid * 16 + (lane & 15)) * ST_F + (lane >> 4) * 8) * 2;
    const uint32_t kOffL = (((lane & 7) + ((lane >> 4) << 3)) * ST_F
                            + ((lane >> 3) & 1) * 8) * 2;
    const uint32_t vOffL = (((lane & 7) + ((lane >> 4) << 3)) * STV) * 2
                            + ((lane >> 3) & 1) * 16;

    // Q tile: 128 rows x 64 fp16 (one group)
    #pragma unroll
    for (int it = 0; it < 4; ++it) {
        int lin = tid + it * 256;
        int r = lin >> 3, c = (lin & 7) * 8;
        cp_async16(smemU + (r * ST_F + c) * 2, gQ + (size_t)r * HDIM + c);
    }
    asm volatile("cp.async.commit_group;" ::: "memory");

    auto loadKV = [&](int jj, int buf) {
        uint32_t kd = smemU + KsB + buf * BKV2 * ST_F * 2;
        uint32_t vd = smemU + VsB + buf * HDIM * STV * 2;
        #pragma unroll
        for (int it = 0; it < 4; ++it) {          // K: 128 rows x 8 chunks
            int lin = tid + it * 256;
            int r = lin >> 3, c = (lin & 7) * 8;
            cp_async16(kd + (r * ST_F + c) * 2, gK + (size_t)(jj * BKV2 + r) * HDIM + c);
        }
        #pragma unroll
        for (int it = 0; it < 4; ++it) {          // V: 64 rows x 16 chunks
            int lin = tid + it * 256;
            int r = lin >> 4, c = (lin & 15) * 8;
            cp_async16(vd + (r * STV + c) * 2, gV + (size_t)r * SEQ + jj * BKV2 + c);
        }
        asm volatile("cp.async.commit_group;" ::: "memory");
    };

    loadKV(0, 0);

    float mrow0 = -1e30f, mrow1 = -1e30f;
    float lrow0 = 0.0f, lrow1 = 0.0f;
    float o[8][4] = {};
    uint32_t qf[4][4];                            // loop-invariant Q fragments

    for (int jj = 0; jj < NJ2; ++jj) {
        asm volatile("cp.async.wait_group 0;" ::: "memory");
        __syncthreads();   // publishes KV jj AND certifies reads of buffer (jj+1)&1 done
        if (jj + 1 < NJ2) loadKV(jj + 1, (jj + 1) & 1);
        if (jj == 0) {
            #pragma unroll
            for (int ks = 0; ks < 4; ++ks)
                ldsm_x4(qf[ks], smemU + qOff + ks * 32);
        }

        #pragma unroll
        for (int sub = 0; sub < 2; ++sub) {
            // ---- S = Q K^T (64 keys; Q pre-scaled by (1/8)*log2e) ----
            float s[8][4] = {};
            const uint32_t kBase = smemU + KsB + (jj & 1) * BKV2 * ST_F * 2
                                   + sub * (64 * ST_F * 2) + kOffL;
            #pragma unroll
            for (int ks = 0; ks < 4; ++ks) {
                #pragma unroll
                for (int np = 0; np < 4; ++np) {
                    uint32_t bq[4];
                    ldsm_x4(bq, kBase + np * (16 * ST_F * 2) + ks * 32);
                    mma_f16(s[2 * np],     qf[ks], bq);
                    mma_f16(s[2 * np + 1], qf[ks], bq + 2);
                }
            }

            // ---- online softmax in base 2 ----
            float mx0 = -1e30f, mx1 = -1e30f;
            #pragma unroll
            for (int nt = 0; nt < 8; ++nt) {
                mx0 = fmaxf(mx0, fmaxf(s[nt][0], s[nt][1]));
                mx1 = fmaxf(mx1, fmaxf(s[nt][2], s[nt][3]));
            }
            mx0 = fmaxf(mx0, __shfl_xor_sync(0xffffffffu, mx0, 1));
            mx0 = fmaxf(mx0, __shfl_xor_sync(0xffffffffu, mx0, 2));
            mx1 = fmaxf(mx1, __shfl_xor_sync(0xffffffffu, mx1, 1));
            mx1 = fmaxf(mx1, __shfl_xor_sync(0xffffffffu, mx1, 2));
            const float mn0 = fmaxf(mrow0, mx0), mn1 = fmaxf(mrow1, mx1);
            const float a0 = ex2(mrow0 - mn0), a1 = ex2(mrow1 - mn1);
            mrow0 = mn0; mrow1 = mn1;

            float sum0 = 0.0f, sum1 = 0.0f;
            #pragma unroll
            for (int nt = 0; nt < 8; ++nt) {
                s[nt][0] = ex2(s[nt][0] - mn0); s[nt][1] = ex2(s[nt][1] - mn0);
                s[nt][2] = ex2(s[nt][2] - mn1); s[nt][3] = ex2(s[nt][3] - mn1);
                sum0 += s[nt][0] + s[nt][1]; sum1 += s[nt][2] + s[nt][3];
            }
            sum0 += __shfl_xor_sync(0xffffffffu, sum0, 1);
            sum0 += __shfl_xor_sync(0xffffffffu, sum0, 2);
            sum1 += __shfl_xor_sync(0xffffffffu, sum1, 1);
            sum1 += __shfl_xor_sync(0xffffffffu, sum1, 2);
            lrow0 = lrow0 * a0 + sum0;
            lrow1 = lrow1 * a1 + sum1;
            #pragma unroll
            for (int nt = 0; nt < 8; ++nt) {
                o[nt][0] *= a0; o[nt][1] *= a0;
                o[nt][2] *= a1; o[nt][3] *= a1;
            }

            // ---- O += P V ----
            const uint32_t vBase = smemU + VsB + (jj & 1) * HDIM * STV * 2
                                   + sub * 128 + vOffL;   // sub*64 halves = 128 B
            #pragma unroll
            for (int kc = 0; kc < 4; ++kc) {
                uint32_t af[4];
                af[0] = pack_h2(s[2 * kc][0],     s[2 * kc][1]);
                af[1] = pack_h2(s[2 * kc][2],     s[2 * kc][3]);
                af[2] = pack_h2(s[2 * kc + 1][0], s[2 * kc + 1][1]);
                af[3] = pack_h2(s[2 * kc + 1][2], s[2 * kc + 1][3]);
                #pragma unroll
                for (int np = 0; np < 4; ++np) {
                    uint32_t bq[4];
                    ldsm_x4(bq, vBase + np * (16 * STV * 2) + kc * 32);
                    mma_f16(o[2 * np],     af, bq);
                    mma_f16(o[2 * np + 1], af, bq + 2);
                }
            }
        }
        // no bottom barrier: next iteration's top sync covers the WAR
    }

    // ---- epilogue: O /= l, fp16 RN, write ctx [B,S,E] ----
    const float inv0 = 1.0f / lrow0, inv1 = 1.0f / lrow1;
    const int rq = wid * 16 + qid;
    const int q0 = blockIdx.x * BQ + rq;
    __half* dst0 = ctx + ((size_t)b * SEQ + q0) * EMBED + h * HDIM;
    __half* dst1 = ctx + ((size_t)b * SEQ + q0 + 8) * EMBED + h * HDIM;
    #pragma unroll
    for (int nt = 0; nt < 8; ++nt) {
        const int d = nt * 8 + tig * 2;
        *(uint32_t*)&dst0[d] = pack_h2(o[nt][0] * inv0, o[nt][1] * inv0);
        *(uint32_t*)&dst1[d] = pack_h2(o[nt][2] * inv1, o[nt][3] * inv1);
    }
}

// ---------------------------------------------------------------------------
// Launch
// ---------------------------------------------------------------------------
#define SMEM_GEMM  (3 * 256 * ST_H * 2)                               // 61440 B
#define SMEM_FLASH ((BQ * ST_F + 2 * BKV2 * ST_F + 2 * HDIM * STV) * 2) // 90112 B -> 2 CTAs/SM

extern "C" void kernel_launch(void* const* d_in, const int* in_sizes, int n_in,
                              void* d_out, int out_size)
{
    (void)in_sizes; (void)n_in; (void)out_size;
    const float* query = (const float*)d_in[0];
    const float* key   = (const float*)d_in[1];
    const float* value = (const float*)d_in[2];
    const float* Wq = (const float*)d_in[3];  const float* bq = (const float*)d_in[4];
    const float* Wk = (const float*)d_in[5];  const float* bk = (const float*)d_in[6];
    const float* Wv = (const float*)d_in[7];  const float* bv = (const float*)d_in[8];
    const float* Wo = (const float*)d_in[9];  const float* bo = (const float*)d_in[10];
    float* out = (float*)d_out;

    __half *QKh, *Vth, *Cxh;
    cudaGetSymbolAddress((void**)&QKh, g_QKh);
    cudaGetSymbolAddress((void**)&Vth, g_Vth);
    cudaGetSymbolAddress((void**)&Cxh, g_ctxh);

    cudaFuncSetAttribute(gemm_proj, cudaFuncAttributeMaxDynamicSharedMemorySize, SMEM_GEMM);
    cudaFuncSetAttribute(gemm_out,  cudaFuncAttributeMaxDynamicSharedMemorySize, SMEM_GEMM);
    cudaFuncSetAttribute(k_flash,   cudaFuncAttributeMaxDynamicSharedMemorySize, SMEM_FLASH);

    // 1) weight absmax; then merged dequant(fp16, Wq pre-scaled) + input cvt
    k_reset<<<1, 32>>>();
    k_absmax<<<dim3(256, 4), 256>>>(Wq, Wk, Wv, Wo);
    k_prep<<<dim3(4096, 4), 256>>>(query, key, value, Wq, Wk, Wv, Wo);

    // 2) fused Q/K/V projections (V written transposed; Q pre-scaled)
    gemm_proj<<<dim3(EMBED / 128, TOKENS / 128, 3), 256, SMEM_GEMM>>>(bq, bk, bv);

    // 3) fused attention -> ctx fp16 [B,S,E]
    const size_t qkOff = (size_t)NBATCH * NHEADS * SEQ * HDIM;
    k_flash<<<dim3(SEQ / BQ, 1, NBATCH * NHEADS), 256, SMEM_FLASH>>>(
        QKh, QKh + qkOff, Vth, Cxh);

    // 4) output projection -> d_out (fp32)
    gemm_out<<<dim3(EMBED / 128, TOKENS / 128, 1), 256, SMEM_GEMM>>>(bo, out);
}

// round 17
// speedup vs baseline: 1.8571x; 1.0572x over previous
#include <cuda_runtime.h>
#include <cuda_fp16.h>
#include <cstdint>

// ---------------------------------------------------------------------------
// Problem constants
// ---------------------------------------------------------------------------
#define EMBED   1024
#define NHEADS  16
#define HDIM    64
#define NBATCH  2
#define SEQ     2048
#define TOKENS  (NBATCH * SEQ)          // 4096
#define WELEMS  (EMBED * EMBED)         // 1048576
#define SCALE_Q 0.18033688f             // (1/8) * log2(e): attn scale + exp2 base folded into Wq/bq
#define ST_G 72                         // GEMM smem row stride (fp16): 64 data + 8 pad (144B)
#define ST_F 72                         // flash K/Q row stride (fp16): 64 data + 8 pad
#define STV  136                        // flash V row stride (fp16): 128 keys + 8 pad

// Flash tiling: 128 keys per load (two 64-key compute sub-tiles)
#define BQ    128
#define BKV2  128
#define NJ2   (SEQ / BKV2)              // 16

// ---------------------------------------------------------------------------
// Scratch (static __device__ globals; no runtime allocation allowed)
// ---------------------------------------------------------------------------
__device__ __half g_Wh[4 * WELEMS];                                   // fp16 dequant weights (Wq pre-scaled)
__device__ int    g_absmax[4];
__device__ __half g_Xh[3 * (size_t)TOKENS * EMBED];                   // fp16 inputs
__device__ __half g_QKh[2 * (size_t)NBATCH * NHEADS * SEQ * HDIM];    // Q(scaled) then K, [B,H,S,D]
__device__ __half g_Vth[(size_t)NBATCH * NHEADS * HDIM * SEQ];        // [B,H,D,S]
__device__ __half g_ctxh[(size_t)TOKENS * EMBED];                     // [B,S,E]

// ---------------------------------------------------------------------------
// Helpers (target-portable: mma.sync sm_80+, cp.async sm_80+, ldmatrix sm_75+)
// ---------------------------------------------------------------------------
__device__ __forceinline__ uint32_t smem_u32(const void* p) {
    uint32_t a;
    asm("{ .reg .u64 t; cvta.to.shared.u64 t, %1; cvt.u32.u64 %0, t; }" : "=r"(a) : "l"(p));
    return a;
}

__device__ __forceinline__ void cp_async16(uint32_t saddr, const void* gaddr) {
    asm volatile("cp.async.cg.shared.global [%0], [%1], 16;"
                 :: "r"(saddr), "l"(gaddr) : "memory");
}

__device__ __forceinline__ void mma_f16(float* d, const uint32_t* a, const uint32_t* b) {
    asm volatile(
        "mma.sync.aligned.m16n8k16.row.col.f32.f16.f16.f32 "
        "{%0,%1,%2,%3}, {%4,%5,%6,%7}, {%8,%9}, {%0,%1,%2,%3};"
        : "+f"(d[0]), "+f"(d[1]), "+f"(d[2]), "+f"(d[3])
        : "r"(a[0]), "r"(a[1]), "r"(a[2]), "r"(a[3]), "r"(b[0]), "r"(b[1]));
}

__device__ __forceinline__ void ldsm_x4(uint32_t* r, uint32_t addr) {
    asm volatile("ldmatrix.sync.aligned.m8n8.x4.shared.b16 {%0,%1,%2,%3}, [%4];"
                 : "=r"(r[0]), "=r"(r[1]), "=r"(r[2]), "=r"(r[3]) : "r"(addr));
}

__device__ __forceinline__ uint32_t pack_h2(float lo, float hi) {
    uint32_t r;
    asm("cvt.rn.f16x2.f32 %0, %1, %2;" : "=r"(r) : "f"(hi), "f"(lo));
    return r;
}

__device__ __forceinline__ float ex2(float x) {
    float r;
    asm("ex2.approx.f32 %0, %1;" : "=f"(r) : "f"(x));
    return r;
}

// ---------------------------------------------------------------------------
// Weight quantization (bit-faithful) + input conversion, one merged pass.
// ---------------------------------------------------------------------------
__global__ void k_reset() { if (threadIdx.x < 4) g_absmax[threadIdx.x] = 0; }

__global__ void k_absmax(const float* __restrict__ w0, const float* __restrict__ w1,
                         const float* __restrict__ w2, const float* __restrict__ w3)
{
    const float* W = (blockIdx.y == 0) ? w0 : (blockIdx.y == 1) ? w1
                   : (blockIdx.y == 2) ? w2 : w3;
    float m = 0.0f;
    for (int i = blockIdx.x * blockDim.x + threadIdx.x; i < WELEMS;
         i += gridDim.x * blockDim.x)
        m = fmaxf(m, fabsf(W[i]));
    #pragma unroll
    for (int o = 16; o; o >>= 1) m = fmaxf(m, __shfl_xor_sync(0xffffffffu, m, o));
    if ((threadIdx.x & 31) == 0) atomicMax(&g_absmax[blockIdx.y], __float_as_int(m));
}

// grid (4096, 4): y<3 -> input cvt (sel=y); y==3 -> weight dequant
__global__ void k_prep(const float* __restrict__ q, const float* __restrict__ k,
                       const float* __restrict__ v,
                       const float* __restrict__ w0, const float* __restrict__ w1,
                       const float* __restrict__ w2, const float* __restrict__ w3)
{
    const int y = blockIdx.y;
    if (y < 3) {
        const float* s = (y == 0) ? q : (y == 1) ? k : v;
        __half* d = g_Xh + (size_t)y * TOKENS * EMBED;
        int i = (blockIdx.x * blockDim.x + threadIdx.x) * 4;
        float4 w = *(const float4*)&s[i];
        *(__half2*)&d[i]     = __floats2half2_rn(w.x, w.y);
        *(__half2*)&d[i + 2] = __floats2half2_rn(w.z, w.w);
    } else {
        const int sel = blockIdx.x >> 10;
        const int bx  = blockIdx.x & 1023;
        const float* W = (sel == 0) ? w0 : (sel == 1) ? w1 : (sel == 2) ? w2 : w3;
        float sc = __int_as_float(g_absmax[sel]) / 127.0f;
        const float post = (sel == 0) ? SCALE_Q : 1.0f;
        int i = (bx * blockDim.x + threadIdx.x) * 4;
        float4 w = *(const float4*)&W[i];
        __half2 h0 = __floats2half2_rn(
            fminf(fmaxf(rintf(w.x / sc), -128.0f), 127.0f) * sc * post,
            fminf(fmaxf(rintf(w.y / sc), -128.0f), 127.0f) * sc * post);
        __half2 h1 = __floats2half2_rn(
            fminf(fmaxf(rintf(w.z / sc), -128.0f), 127.0f) * sc * post,
            fminf(fmaxf(rintf(w.w / sc), -128.0f), 127.0f) * sc * post);
        *(__half2*)&g_Wh[(size_t)sel * WELEMS + i]     = h0;
        *(__half2*)&g_Wh[(size_t)sel * WELEMS + i + 2] = h1;
    }
}

// ---------------------------------------------------------------------------
// fp16 NT GEMM mainloop (m16n8k16): BK=64 per stage (stride ST_G=72, banks
// 4r mod 32 conflict-free), NS=3 -> 16 barriers total, 128-column prefetch
// horizon, 4 independent ks-chunks (64 mmas) between barriers.
// k-summation order identical to BK=32 version -> bit-identical results.
// ---------------------------------------------------------------------------
#define GEMM_MAINLOOP(SMEMU, GA, GB, ACC)                                        \
    const uint32_t aOff = ((wm * 64 + (lane & 15)) * ST_G + (lane >> 4) * 8) * 2;\
    const uint32_t bOff = ((wn * 32 + (lane & 7) + ((lane >> 4) << 3)) * ST_G    \
                           + ((lane >> 3) & 1) * 8) * 2;                         \
    auto loadStage = [&](int st, int k0) {                                       \
        uint32_t sAp = (SMEMU) + st * (256 * ST_G * 2);                          \
        uint32_t sBp = sAp + 128 * ST_G * 2;                                     \
        _Pragma("unroll")                                                        \
        for (int it = 0; it < 4; ++it) {                                         \
            int lin = tid + it * 256;                                            \
            int r = lin >> 3, c = (lin & 7) * 8;                                 \
            cp_async16(sAp + (r * ST_G + c) * 2, (GA) + (size_t)r * EMBED + k0 + c); \
        }                                                                        \
        _Pragma("unroll")                                                        \
        for (int it = 0; it < 4; ++it) {                                         \
            int lin = tid + it * 256;                                            \
            int r = lin >> 3, c = (lin & 7) * 8;                                 \
            cp_async16(sBp + (r * ST_G + c) * 2, (GB) + (size_t)r * EMBED + k0 + c); \
        }                                                                        \
        asm volatile("cp.async.commit_group;" ::: "memory");                     \
    };                                                                           \
    const int ns = EMBED / 64;                                                   \
    loadStage(0, 0);                                                             \
    loadStage(1, 64);                                                            \
    for (int i = 0; i < ns; ++i) {                                               \
        if (i + 1 < ns) { asm volatile("cp.async.wait_group 1;" ::: "memory"); } \
        else            { asm volatile("cp.async.wait_group 0;" ::: "memory"); } \
        __syncthreads();                                                         \
        if (i + 2 < ns) loadStage((i + 2) % 3, (i + 2) * 64);                    \
        const uint32_t aBase = (SMEMU) + (i % 3) * (256 * ST_G * 2) + aOff;      \
        const uint32_t bBase = (SMEMU) + (i % 3) * (256 * ST_G * 2)              \
                               + 128 * ST_G * 2 + bOff;                          \
        _Pragma("unroll")                                                        \
        for (int ks = 0; ks < 4; ++ks) {                                         \
            uint32_t af[4][4], bq[2][4];                                         \
            _Pragma("unroll")                                                    \
            for (int mt = 0; mt < 4; ++mt)                                       \
                ldsm_x4(af[mt], aBase + mt * (16 * ST_G * 2) + ks * 32);         \
            _Pragma("unroll")                                                    \
            for (int np = 0; np < 2; ++np)                                       \
                ldsm_x4(bq[np], bBase + np * (16 * ST_G * 2) + ks * 32);         \
            _Pragma("unroll")                                                    \
            for (int mt = 0; mt < 4; ++mt)                                       \
                _Pragma("unroll")                                                \
                for (int nt = 0; nt < 4; ++nt)                                   \
                    mma_f16(ACC[mt][nt], af[mt], &bq[nt >> 1][(nt & 1) * 2]);    \
        }                                                                        \
    }

// ---------------------------------------------------------------------------
// Fused Q/K/V projection (grid z in {0,1,2}); fp16 in, fp16 out.
// ---------------------------------------------------------------------------
__global__ __launch_bounds__(256, 2)
void gemm_proj(const float* __restrict__ b0, const float* __restrict__ b1,
               const float* __restrict__ b2)
{
    extern __shared__ __half smem[];
    const uint32_t smemU = smem_u32(smem);
    const int tid  = threadIdx.x;
    const int wid  = tid >> 5, lane = tid & 31;
    const int wm   = wid & 1, wn = wid >> 1;
    const int qid  = lane >> 2, tig = lane & 3;
    const int z    = blockIdx.z;

    const float* bias = (z == 0) ? b0 : (z == 1) ? b1 : b2;
    const float bscale = (z == 0) ? SCALE_Q : 1.0f;
    const __half* gA = g_Xh + (size_t)z * TOKENS * EMBED + (size_t)(blockIdx.y * 128) * EMBED;
    const __half* gB = g_Wh + (size_t)z * WELEMS + (size_t)(blockIdx.x * 128) * EMBED;

    float acc[4][4][4] = {};
    GEMM_MAINLOOP(smemU, gA, gB, acc)

    #pragma unroll
    for (int mt = 0; mt < 4; ++mt) {
        const int m = blockIdx.y * 128 + wm * 64 + mt * 16 + qid;
        const int b = m >> 11, s2 = m & (SEQ - 1);
        #pragma unroll
        for (int nt = 0; nt < 4; ++nt) {
            const int n = blockIdx.x * 128 + wn * 32 + nt * 8 + tig * 2;
            const int h = n >> 6, d = n & (HDIM - 1);
            const float bb0 = bias[n] * bscale, bb1 = bias[n + 1] * bscale;
            const float c0 = acc[mt][nt][0] + bb0, c1 = acc[mt][nt][1] + bb1;
            const float c2 = acc[mt][nt][2] + bb0, c3 = acc[mt][nt][3] + bb1;
            if (z < 2) {
                __half* C = g_QKh + (size_t)z * ((size_t)NBATCH * NHEADS * SEQ * HDIM);
                const size_t base = ((size_t)b * NHEADS + h) * SEQ;
                *(uint32_t*)&C[(base + s2) * HDIM + d]     = pack_h2(c0, c1);
                *(uint32_t*)&C[(base + s2 + 8) * HDIM + d] = pack_h2(c2, c3);
            } else {
                const size_t base = ((size_t)b * NHEADS + h) * HDIM;
                g_Vth[(base + d)     * SEQ + s2]     = __float2half_rn(c0);
                g_Vth[(base + d + 1) * SEQ + s2]     = __float2half_rn(c1);
                g_Vth[(base + d)     * SEQ + s2 + 8] = __float2half_rn(c2);
                g_Vth[(base + d + 1) * SEQ + s2 + 8] = __float2half_rn(c3);
            }
        }
    }
}

// ---------------------------------------------------------------------------
// Output projection: fp16 operands, fp32 result to d_out.
// ---------------------------------------------------------------------------
__global__ __launch_bounds__(256, 2)
void gemm_out(const float* __restrict__ bias, float* __restrict__ C)
{
    extern __shared__ __half smem[];
    const uint32_t smemU = smem_u32(smem);
    const int tid  = threadIdx.x;
    const int wid  = tid >> 5, lane = tid & 31;
    const int wm   = wid & 1, wn = wid >> 1;
    const int qid  = lane >> 2, tig = lane & 3;

    const __half* gA = g_ctxh + (size_t)(blockIdx.y * 128) * EMBED;
    const __half* gB = g_Wh + 3 * (size_t)WELEMS + (size_t)(blockIdx.x * 128) * EMBED;

    float acc[4][4][4] = {};
    GEMM_MAINLOOP(smemU, gA, gB, acc)

    #pragma unroll
    for (int mt = 0; mt < 4; ++mt) {
        const int m = blockIdx.y * 128 + wm * 64 + mt * 16 + qid;
        #pragma unroll
        for (int nt = 0; nt < 4; ++nt) {
            const int n = blockIdx.x * 128 + wn * 32 + nt * 8 + tig * 2;
            const float b0 = bias[n], b1 = bias[n + 1];
            *(float2*)&C[(size_t)m * EMBED + n] =
                make_float2(acc[mt][nt][0] + b0, acc[mt][nt][1] + b1);
            *(float2*)&C[(size_t)(m + 8) * EMBED + n] =
                make_float2(acc[mt][nt][2] + b0, acc[mt][nt][3] + b1);
        }
    }
}

// ---------------------------------------------------------------------------
// Fused flash attention (R16 winner, frozen): fp16 m16n8k16, ldmatrix,
// 128-key loads, base-2 softmax with scale folded into Q, hoisted Q frags.
// ---------------------------------------------------------------------------
__global__ __launch_bounds__(256, 2)
void k_flash(const __half* __restrict__ Qg, const __half* __restrict__ Kg,
             const __half* __restrict__ Vtg, __half* __restrict__ ctx)
{
    extern __shared__ __half sm[];
    const uint32_t smemU = smem_u32(sm);
    const uint32_t KsB = BQ * ST_F * 2;               // K ring base (bytes)
    const uint32_t VsB = KsB + 2 * BKV2 * ST_F * 2;   // V ring base

    const int tid = threadIdx.x;
    const int wid = tid >> 5, lane = tid & 31;
    const int qid = lane >> 2, tig = lane & 3;
    const int bh = blockIdx.z;
    const int b = bh >> 4, h = bh & 15;

    const __half* gQ = Qg + ((size_t)bh * SEQ + blockIdx.x * BQ) * HDIM;
    const __half* gK = Kg + (size_t)bh * SEQ * HDIM;
    const __half* gV = Vtg + (size_t)bh * HDIM * SEQ;

    const uint32_t qOff  = ((wid * 16 + (lane & 15)) * ST_F + (lane >> 4) * 8) * 2;
    const uint32_t kOffL = (((lane & 7) + ((lane >> 4) << 3)) * ST_F
                            + ((lane >> 3) & 1) * 8) * 2;
    const uint32_t vOffL = (((lane & 7) + ((lane >> 4) << 3)) * STV) * 2
                            + ((lane >> 3) & 1) * 16;

    #pragma unroll
    for (int it = 0; it < 4; ++it) {
        int lin = tid + it * 256;
        int r = lin >> 3, c = (lin & 7) * 8;
        cp_async16(smemU + (r * ST_F + c) * 2, gQ + (size_t)r * HDIM + c);
    }
    asm volatile("cp.async.commit_group;" ::: "memory");

    auto loadKV = [&](int jj, int buf) {
        uint32_t kd = smemU + KsB + buf * BKV2 * ST_F * 2;
        uint32_t vd = smemU + VsB + buf * HDIM * STV * 2;
        #pragma unroll
        for (int it = 0; it < 4; ++it) {
            int lin = tid + it * 256;
            int r = lin >> 3, c = (lin & 7) * 8;
            cp_async16(kd + (r * ST_F + c) * 2, gK + (size_t)(jj * BKV2 + r) * HDIM + c);
        }
        #pragma unroll
        for (int it = 0; it < 4; ++it) {
            int lin = tid + it * 256;
            int r = lin >> 4, c = (lin & 15) * 8;
            cp_async16(vd + (r * STV + c) * 2, gV + (size_t)r * SEQ + jj * BKV2 + c);
        }
        asm volatile("cp.async.commit_group;" ::: "memory");
    };

    loadKV(0, 0);

    float mrow0 = -1e30f, mrow1 = -1e30f;
    float lrow0 = 0.0f, lrow1 = 0.0f;
    float o[8][4] = {};
    uint32_t qf[4][4];

    for (int jj = 0; jj < NJ2; ++jj) {
        asm volatile("cp.async.wait_group 0;" ::: "memory");
        __syncthreads();
        if (jj + 1 < NJ2) loadKV(jj + 1, (jj + 1) & 1);
        if (jj == 0) {
            #pragma unroll
            for (int ks = 0; ks < 4; ++ks)
                ldsm_x4(qf[ks], smemU + qOff + ks * 32);
        }

        #pragma unroll
        for (int sub = 0; sub < 2; ++sub) {
            float s[8][4] = {};
            const uint32_t kBase = smemU + KsB + (jj & 1) * BKV2 * ST_F * 2
                                   + sub * (64 * ST_F * 2) + kOffL;
            #pragma unroll
            for (int ks = 0; ks < 4; ++ks) {
                #pragma unroll
                for (int np = 0; np < 4; ++np) {
                    uint32_t bq[4];
                    ldsm_x4(bq, kBase + np * (16 * ST_F * 2) + ks * 32);
                    mma_f16(s[2 * np],     qf[ks], bq);
                    mma_f16(s[2 * np + 1], qf[ks], bq + 2);
                }
            }

            float mx0 = -1e30f, mx1 = -1e30f;
            #pragma unroll
            for (int nt = 0; nt < 8; ++nt) {
                mx0 = fmaxf(mx0, fmaxf(s[nt][0], s[nt][1]));
                mx1 = fmaxf(mx1, fmaxf(s[nt][2], s[nt][3]));
            }
            mx0 = fmaxf(mx0, __shfl_xor_sync(0xffffffffu, mx0, 1));
            mx0 = fmaxf(mx0, __shfl_xor_sync(0xffffffffu, mx0, 2));
            mx1 = fmaxf(mx1, __shfl_xor_sync(0xffffffffu, mx1, 1));
            mx1 = fmaxf(mx1, __shfl_xor_sync(0xffffffffu, mx1, 2));
            const float mn0 = fmaxf(mrow0, mx0), mn1 = fmaxf(mrow1, mx1);
            const float a0 = ex2(mrow0 - mn0), a1 = ex2(mrow1 - mn1);
            mrow0 = mn0; mrow1 = mn1;

            float sum0 = 0.0f, sum1 = 0.0f;
            #pragma unroll
            for (int nt = 0; nt < 8; ++nt) {
                s[nt][0] = ex2(s[nt][0] - mn0); s[nt][1] = ex2(s[nt][1] - mn0);
                s[nt][2] = ex2(s[nt][2] - mn1); s[nt][3] = ex2(s[nt][3] - mn1);
                sum0 += s[nt][0] + s[nt][1]; sum1 += s[nt][2] + s[nt][3];
            }
            sum0 += __shfl_xor_sync(0xffffffffu, sum0, 1);
            sum0 += __shfl_xor_sync(0xffffffffu, sum0, 2);
            sum1 += __shfl_xor_sync(0xffffffffu, sum1, 1);
            sum1 += __shfl_xor_sync(0xffffffffu, sum1, 2);
            lrow0 = lrow0 * a0 + sum0;
            lrow1 = lrow1 * a1 + sum1;
            #pragma unroll
            for (int nt = 0; nt < 8; ++nt) {
                o[nt][0] *= a0; o[nt][1] *= a0;
                o[nt][2] *= a1; o[nt][3] *= a1;
            }

            const uint32_t vBase = smemU + VsB + (jj & 1) * HDIM * STV * 2
                                   + sub * 128 + vOffL;
            #pragma unroll
            for (int kc = 0; kc < 4; ++kc) {
                uint32_t af[4];
                af[0] = pack_h2(s[2 * kc][0],     s[2 * kc][1]);
                af[1] = pack_h2(s[2 * kc][2],     s[2 * kc][3]);
                af[2] = pack_h2(s[2 * kc + 1][0], s[2 * kc + 1][1]);
                af[3] = pack_h2(s[2 * kc + 1][2], s[2 * kc + 1][3]);
                #pragma unroll
                for (int np = 0; np < 4; ++np) {
                    uint32_t bq[4];
                    ldsm_x4(bq, vBase + np * (16 * STV * 2) + kc * 32);
                    mma_f16(o[2 * np],     af, bq);
                    mma_f16(o[2 * np + 1], af, bq + 2);
                }
            }
        }
    }

    const float inv0 = 1.0f / lrow0, inv1 = 1.0f / lrow1;
    const int rq = wid * 16 + qid;
    const int q0 = blockIdx.x * BQ + rq;
    __half* dst0 = ctx + ((size_t)b * SEQ + q0) * EMBED + h * HDIM;
    __half* dst1 = ctx + ((size_t)b * SEQ + q0 + 8) * EMBED + h * HDIM;
    #pragma unroll
    for (int nt = 0; nt < 8; ++nt) {
        const int d = nt * 8 + tig * 2;
        *(uint32_t*)&dst0[d] = pack_h2(o[nt][0] * inv0, o[nt][1] * inv0);
        *(uint32_t*)&dst1[d] = pack_h2(o[nt][2] * inv1, o[nt][3] * inv1);
    }
}

// ---------------------------------------------------------------------------
// Launch
// ---------------------------------------------------------------------------
#define SMEM_GEMM  (3 * 256 * ST_G * 2)                               // 110592 B -> 2 CTAs/SM
#define SMEM_FLASH ((BQ * ST_F + 2 * BKV2 * ST_F + 2 * HDIM * STV) * 2) // 90112 B -> 2 CTAs/SM

extern "C" void kernel_launch(void* const* d_in, const int* in_sizes, int n_in,
                              void* d_out, int out_size)
{
    (void)in_sizes; (void)n_in; (void)out_size;
    const float* query = (const float*)d_in[0];
    const float* key   = (const float*)d_in[1];
    const float* value = (const float*)d_in[2];
    const float* Wq = (const float*)d_in[3];  const float* bq = (const float*)d_in[4];
    const float* Wk = (const float*)d_in[5];  const float* bk = (const float*)d_in[6];
    const float* Wv = (const float*)d_in[7];  const float* bv = (const float*)d_in[8];
    const float* Wo = (const float*)d_in[9];  const float* bo = (const float*)d_in[10];
    float* out = (float*)d_out;

    __half *QKh, *Vth, *Cxh;
    cudaGetSymbolAddress((void**)&QKh, g_QKh);
    cudaGetSymbolAddress((void**)&Vth, g_Vth);
    cudaGetSymbolAddress((void**)&Cxh, g_ctxh);

    cudaFuncSetAttribute(gemm_proj, cudaFuncAttributeMaxDynamicSharedMemorySize, SMEM_GEMM);
    cudaFuncSetAttribute(gemm_out,  cudaFuncAttributeMaxDynamicSharedMemorySize, SMEM_GEMM);
    cudaFuncSetAttribute(k_flash,   cudaFuncAttributeMaxDynamicSharedMemorySize, SMEM_FLASH);

    // 1) weight absmax; merged dequant(fp16, Wq pre-scaled) + input cvt
    k_reset<<<1, 32>>>();
    k_absmax<<<dim3(256, 4), 256>>>(Wq, Wk, Wv, Wo);
    k_prep<<<dim3(4096, 4), 256>>>(query, key, value, Wq, Wk, Wv, Wo);

    // 2) fused Q/K/V projections (V written transposed; Q pre-scaled)
    gemm_proj<<<dim3(EMBED / 128, TOKENS / 128, 3), 256, SMEM_GEMM>>>(bq, bk, bv);

    // 3) fused attention -> ctx fp16 [B,S,E]
    const size_t qkOff = (size_t)NBATCH * NHEADS * SEQ * HDIM;
    k_flash<<<dim3(SEQ / BQ, 1, NBATCH * NHEADS), 256, SMEM_FLASH>>>(
        QKh, QKh + qkOff, Vth, Cxh);

    // 4) output projection -> d_out (fp32)
    gemm_out<<<dim3(EMBED / 128, TOKENS / 128, 1), 256, SMEM_GEMM>>>(bo, out);
}